// round 3
// baseline (speedup 1.0000x reference)
#include <cuda_runtime.h>
#include <math.h>

#define B_   2
#define T_   1024
#define E_   512
#define NH_  8
#define HD_  64
#define BNH_ 16
#define QKVLD (3*E_)   // 1536

// ---------------- scratch (device globals: allocation-free) ----------------
__device__ float g_qkv[B_*T_*3*E_];          // (2048, 1536) rows = b*T+t
__device__ float g_params[BNH_*T_*6];        // per (g,t): bl, br, al, dist, bl-start, end-br
__device__ float g_scores[(size_t)BNH_*T_*T_]; // 64 MB
__device__ float g_attnout[B_*T_*E_];        // (2048, 512)

// ---------------- generic SGEMM + bias: 128x128x8 tile, 8x8 microtile ------
__global__ __launch_bounds__(256) void sgemm_bias_128(
    int M, int N, int K,
    const float* __restrict__ A, int lda,
    const float* __restrict__ Bm, int ldb,
    const float* __restrict__ bias,
    float* __restrict__ C, int ldc)
{
    __shared__ float As[8][128];
    __shared__ float Bs[8][128];
    const int tid = threadIdx.x;
    const int tx = tid & 15, ty = tid >> 4;
    const int m0 = blockIdx.y * 128, n0 = blockIdx.x * 128;

    float acc[8][8];
#pragma unroll
    for (int i = 0; i < 8; i++)
#pragma unroll
        for (int j = 0; j < 8; j++) acc[i][j] = 0.f;

    const int am = tid >> 1, ak = (tid & 1) * 4;
    const int bk = tid >> 5, bc = (tid & 31) * 4;

    for (int k0 = 0; k0 < K; k0 += 8) {
        float4 av = *(const float4*)&A[(size_t)(m0 + am) * lda + k0 + ak];
        As[ak + 0][am] = av.x; As[ak + 1][am] = av.y;
        As[ak + 2][am] = av.z; As[ak + 3][am] = av.w;
        *(float4*)&Bs[bk][bc] = *(const float4*)&Bm[(size_t)(k0 + bk) * ldb + n0 + bc];
        __syncthreads();
#pragma unroll
        for (int k = 0; k < 8; k++) {
            float4 a0 = *(float4*)&As[k][ty * 4];
            float4 a1 = *(float4*)&As[k][64 + ty * 4];
            float4 b0 = *(float4*)&Bs[k][tx * 4];
            float4 b1 = *(float4*)&Bs[k][64 + tx * 4];
            float a[8] = {a0.x, a0.y, a0.z, a0.w, a1.x, a1.y, a1.z, a1.w};
            float b[8] = {b0.x, b0.y, b0.z, b0.w, b1.x, b1.y, b1.z, b1.w};
#pragma unroll
            for (int i = 0; i < 8; i++)
#pragma unroll
                for (int j = 0; j < 8; j++)
                    acc[i][j] = fmaf(a[i], b[j], acc[i][j]);
        }
        __syncthreads();
    }

#pragma unroll
    for (int ih = 0; ih < 2; ih++)
#pragma unroll
        for (int di = 0; di < 4; di++) {
            int m = m0 + ih * 64 + ty * 4 + di;
#pragma unroll
            for (int jh = 0; jh < 2; jh++) {
                int n = n0 + jh * 64 + tx * 4;
                float4 v;
                v.x = acc[ih * 4 + di][jh * 4 + 0] + bias[n + 0];
                v.y = acc[ih * 4 + di][jh * 4 + 1] + bias[n + 1];
                v.z = acc[ih * 4 + di][jh * 4 + 2] + bias[n + 2];
                v.w = acc[ih * 4 + di][jh * 4 + 3] + bias[n + 3];
                *(float4*)&C[(size_t)m * ldc + n] = v;
            }
        }
}

// ---------------- params: od = Q @ W_od + b_od, then offsets/durations -----
__device__ __forceinline__ float decode_len(const void* p)
{
    int iv = *(const int*)p;
    if (iv > 0 && iv < (1 << 24)) return (float)iv;   // int32 scalar
    return __int_as_float(iv);                         // float32 scalar
}

__global__ void params_kernel(const float* __restrict__ W_od,
                              const float* __restrict__ b_od,
                              const void*  __restrict__ lenraw)
{
    const int row = blockIdx.x;              // 0..2047
    const int b = row >> 10, t = row & 1023;
    const int tid = threadIdx.x;
    const int w = tid >> 5, lane = tid & 31; // 16 warps, one per od column
    const float* q = g_qkv + (size_t)row * QKVLD;  // Q slice = first E cols

    float s = 0.f;
    for (int k = lane; k < E_; k += 32)
        s = fmaf(q[k], W_od[k * (2 * NH_) + w], s);
#pragma unroll
    for (int o = 16; o; o >>= 1) s += __shfl_xor_sync(0xffffffffu, s, o);

    __shared__ float od[2 * NH_];
    if (lane == 0) od[w] = s + b_od[w];
    __syncthreads();

    if (tid < NH_) {
        const int h = tid;
        const float len = decode_len(lenraw);
        float off = tanhf(od[h]) * len;
        float dur = (1.f / (1.f + expf(-od[NH_ + h]))) * len;
        float anchor = (float)t + off;
        float start = anchor - dur;
        float end   = anchor + dur;
        float bl = floorf(start);
        float br = ceilf(end);
        float al = floorf(anchor);
        float dist = anchor - al;
        int g = b * NH_ + h;
        float* p = g_params + (size_t)(g * T_ + t) * 6;
        p[0] = bl; p[1] = br; p[2] = al; p[3] = dist;
        p[4] = bl - start; p[5] = end - br;
    }
}

// ---------------- scores = (Q K^T * scale) * point_weight, masked ----------
__global__ __launch_bounds__(256) void scores_kernel()
{
    const int g = blockIdx.z, b = g >> 3, h = g & 7;
    const int i0 = blockIdx.y * 128, r0 = blockIdx.x * 128;
    const float* Qb = g_qkv + (size_t)(b * T_) * QKVLD + h * HD_;            // Q[i][c]
    const float* Kb = g_qkv + (size_t)(b * T_) * QKVLD + E_ + h * HD_;       // K[r][c]

    __shared__ float Qs[8][128];
    __shared__ float Ks[8][128];
    __shared__ float Ps[128][6];

    const int tid = threadIdx.x;
    const int tx = tid & 15, ty = tid >> 4;

    // stage per-query params for this i-tile
    for (int idx = tid; idx < 128 * 6; idx += 256)
        ((float*)Ps)[idx] = g_params[(size_t)(g * T_ + i0) * 6 + idx];

    float acc[8][8];
#pragma unroll
    for (int i = 0; i < 8; i++)
#pragma unroll
        for (int j = 0; j < 8; j++) acc[i][j] = 0.f;

    const int am = tid >> 1, ak = (tid & 1) * 4;

    for (int c0 = 0; c0 < HD_; c0 += 8) {
        float4 qv = *(const float4*)&Qb[(size_t)(i0 + am) * QKVLD + c0 + ak];
        Qs[ak + 0][am] = qv.x; Qs[ak + 1][am] = qv.y;
        Qs[ak + 2][am] = qv.z; Qs[ak + 3][am] = qv.w;
        float4 kv = *(const float4*)&Kb[(size_t)(r0 + am) * QKVLD + c0 + ak];
        Ks[ak + 0][am] = kv.x; Ks[ak + 1][am] = kv.y;
        Ks[ak + 2][am] = kv.z; Ks[ak + 3][am] = kv.w;
        __syncthreads();
#pragma unroll
        for (int k = 0; k < 8; k++) {
            float4 a0 = *(float4*)&Qs[k][ty * 4];
            float4 a1 = *(float4*)&Qs[k][64 + ty * 4];
            float4 b0 = *(float4*)&Ks[k][tx * 4];
            float4 b1 = *(float4*)&Ks[k][64 + tx * 4];
            float a[8] = {a0.x, a0.y, a0.z, a0.w, a1.x, a1.y, a1.z, a1.w};
            float bb[8] = {b0.x, b0.y, b0.z, b0.w, b1.x, b1.y, b1.z, b1.w};
#pragma unroll
            for (int i = 0; i < 8; i++)
#pragma unroll
                for (int j = 0; j < 8; j++)
                    acc[i][j] = fmaf(a[i], bb[j], acc[i][j]);
        }
        __syncthreads();
    }

    const float scaling = 0.125f;  // 64^-0.5
#pragma unroll
    for (int ih = 0; ih < 2; ih++)
#pragma unroll
        for (int di = 0; di < 4; di++) {
            int il = ih * 64 + ty * 4 + di;
            float bl = Ps[il][0], br = Ps[il][1], al = Ps[il][2];
            float dist = Ps[il][3], wl = Ps[il][4], wr = Ps[il][5];
            float* out = g_scores + (size_t)g * (T_ * T_) + (size_t)(i0 + il) * T_;
#pragma unroll
            for (int jh = 0; jh < 2; jh++) {
                int rbase = r0 + jh * 64 + tx * 4;
                float4 v;
                float* vv = &v.x;
#pragma unroll
                for (int dj = 0; dj < 4; dj++) {
                    float rf = (float)(rbase + dj);
                    float s = acc[ih * 4 + di][jh * 4 + dj] * scaling;
                    float w = 1.f;
                    if (rf == bl) w += wl;
                    if (rf == br) w += wr;
                    if (rf == al + 1.f) w += dist;
                    if (rf == al) w += 1.f - dist;
                    s *= w;
                    if (rf < bl || rf > br) s = -1e8f;
                    vv[dj] = s;
                }
                *(float4*)&out[rbase] = v;
            }
        }
}

// ---------------- row softmax over 1024 keys -------------------------------
__global__ __launch_bounds__(256) void softmax_kernel()
{
    const int row = blockIdx.x;                 // 0..16383
    float* p = g_scores + (size_t)row * T_;
    const int tid = threadIdx.x;
    __shared__ float red[256];

    float4 v = *(float4*)&p[tid * 4];
    float m = fmaxf(fmaxf(v.x, v.y), fmaxf(v.z, v.w));
    red[tid] = m;
    __syncthreads();
#pragma unroll
    for (int o = 128; o; o >>= 1) {
        if (tid < o) red[tid] = fmaxf(red[tid], red[tid + o]);
        __syncthreads();
    }
    m = red[0];
    __syncthreads();

    v.x = expf(v.x - m); v.y = expf(v.y - m);
    v.z = expf(v.z - m); v.w = expf(v.w - m);
    red[tid] = v.x + v.y + v.z + v.w;
    __syncthreads();
#pragma unroll
    for (int o = 128; o; o >>= 1) {
        if (tid < o) red[tid] += red[tid + o];
        __syncthreads();
    }
    float inv = 1.f / red[0];
    v.x *= inv; v.y *= inv; v.z *= inv; v.w *= inv;
    *(float4*)&p[tid * 4] = v;
}

// ---------------- out = attn @ V, scattered to (b,t,e) layout --------------
__global__ __launch_bounds__(256) void av_kernel()
{
    const int g = blockIdx.z, b = g >> 3, h = g & 7;
    const int i0 = blockIdx.y * 128;
    const float* Aat = g_scores + (size_t)g * (T_ * T_);                 // [i][r], ld=1024
    const float* Vb  = g_qkv + (size_t)(b * T_) * QKVLD + 2 * E_ + h * HD_; // V[r][c], ld=1536

    __shared__ float As[16][128];
    __shared__ float Bs[16][64];
    const int tid = threadIdx.x;
    const int tx = tid & 15, ty = tid >> 4;

    float acc[8][4];
#pragma unroll
    for (int i = 0; i < 8; i++)
#pragma unroll
        for (int j = 0; j < 4; j++) acc[i][j] = 0.f;

    const int am = tid >> 1, akb = (tid & 1) * 8;
    const int bk = tid >> 4, bc = (tid & 15) * 4;

    for (int k0 = 0; k0 < T_; k0 += 16) {
        float4 a0v = *(const float4*)&Aat[(size_t)(i0 + am) * T_ + k0 + akb];
        float4 a1v = *(const float4*)&Aat[(size_t)(i0 + am) * T_ + k0 + akb + 4];
        As[akb + 0][am] = a0v.x; As[akb + 1][am] = a0v.y;
        As[akb + 2][am] = a0v.z; As[akb + 3][am] = a0v.w;
        As[akb + 4][am] = a1v.x; As[akb + 5][am] = a1v.y;
        As[akb + 6][am] = a1v.z; As[akb + 7][am] = a1v.w;
        *(float4*)&Bs[bk][bc] = *(const float4*)&Vb[(size_t)(k0 + bk) * QKVLD + bc];
        __syncthreads();
#pragma unroll
        for (int k = 0; k < 16; k++) {
            float4 a0 = *(float4*)&As[k][ty * 4];
            float4 a1 = *(float4*)&As[k][64 + ty * 4];
            float4 bb = *(float4*)&Bs[k][tx * 4];
            float a[8] = {a0.x, a0.y, a0.z, a0.w, a1.x, a1.y, a1.z, a1.w};
            float bv[4] = {bb.x, bb.y, bb.z, bb.w};
#pragma unroll
            for (int i = 0; i < 8; i++)
#pragma unroll
                for (int j = 0; j < 4; j++)
                    acc[i][j] = fmaf(a[i], bv[j], acc[i][j]);
        }
        __syncthreads();
    }

    float* O = g_attnout + (size_t)(b * T_) * E_ + h * HD_;
#pragma unroll
    for (int ih = 0; ih < 2; ih++)
#pragma unroll
        for (int di = 0; di < 4; di++) {
            int i = i0 + ih * 64 + ty * 4 + di;
            float4 v;
            v.x = acc[ih * 4 + di][0]; v.y = acc[ih * 4 + di][1];
            v.z = acc[ih * 4 + di][2]; v.w = acc[ih * 4 + di][3];
            *(float4*)&O[(size_t)i * E_ + tx * 4] = v;
        }
}

// ---------------- host launch ----------------------------------------------
extern "C" void kernel_launch(void* const* d_in, const int* in_sizes, int n_in,
                              void* d_out, int out_size)
{
    const float* x      = (const float*)d_in[0];
    const float* W_qkv  = (const float*)d_in[1];
    const float* b_qkv  = (const float*)d_in[2];
    const float* W_od   = (const float*)d_in[3];
    const float* b_od   = (const float*)d_in[4];
    const float* W_out  = (const float*)d_in[5];
    const float* b_out  = (const float*)d_in[6];
    const void*  lenp   = (const void*)d_in[7];
    float* out = (float*)d_out;

    static float* qkv_p = nullptr;
    static float* attnout_p = nullptr;
    if (!qkv_p) {
        cudaGetSymbolAddress((void**)&qkv_p, g_qkv);
        cudaGetSymbolAddress((void**)&attnout_p, g_attnout);
    }

    // 1) qkv = x @ W_qkv + b_qkv       (2048 x 1536 x 512)
    sgemm_bias_128<<<dim3(QKVLD / 128, (B_ * T_) / 128), 256>>>(
        B_ * T_, QKVLD, E_, x, E_, W_qkv, QKVLD, b_qkv, qkv_p, QKVLD);

    // 2) od projection + per-(head,query) band parameters
    params_kernel<<<B_ * T_, 512>>>(W_od, b_od, lenp);

    // 3) scores = (Q K^T * scale) * point_weight, masked
    scores_kernel<<<dim3(T_ / 128, T_ / 128, BNH_), 256>>>();

    // 4) softmax
    softmax_kernel<<<BNH_ * T_, 256>>>();

    // 5) out_heads = attn @ V  -> (b,t,e)
    av_kernel<<<dim3(1, T_ / 128, BNH_), 256>>>();

    // 6) result = attn_out @ W_out + b_out   (2048 x 512 x 512)
    sgemm_bias_128<<<dim3(E_ / 128, (B_ * T_) / 128), 256>>>(
        B_ * T_, E_, E_, attnout_p, E_, W_out, E_, b_out, out, E_);
}

// round 4
// speedup vs baseline: 1.1984x; 1.1984x over previous
#include <cuda_runtime.h>
#include <math.h>

#define B_   2
#define T_   1024
#define E_   512
#define NH_  8
#define HD_  64
#define BNH_ 16
#define QKVLD (3*E_)   // 1536

// ---------------- scratch (device globals: allocation-free) ----------------
__device__ float g_qkv[B_*T_*3*E_];          // (2048, 1536) rows = b*T+t
__device__ float g_params[BNH_*T_*6];        // per (g,t): bl, br, al, dist, bl-start, end-br
__device__ float g_attnout[B_*T_*E_];        // (2048, 512)

// ---------------- generic SGEMM + bias: 128x128x8 tile, 8x8 microtile ------
__global__ __launch_bounds__(256) void sgemm_bias_128(
    int M, int N, int K,
    const float* __restrict__ A, int lda,
    const float* __restrict__ Bm, int ldb,
    const float* __restrict__ bias,
    float* __restrict__ C, int ldc)
{
    __shared__ float As[8][128];
    __shared__ float Bs[8][128];
    const int tid = threadIdx.x;
    const int tx = tid & 15, ty = tid >> 4;
    const int m0 = blockIdx.y * 128, n0 = blockIdx.x * 128;

    float acc[8][8];
#pragma unroll
    for (int i = 0; i < 8; i++)
#pragma unroll
        for (int j = 0; j < 8; j++) acc[i][j] = 0.f;

    const int am = tid >> 1, ak = (tid & 1) * 4;
    const int bk = tid >> 5, bc = (tid & 31) * 4;

    for (int k0 = 0; k0 < K; k0 += 8) {
        float4 av = *(const float4*)&A[(size_t)(m0 + am) * lda + k0 + ak];
        As[ak + 0][am] = av.x; As[ak + 1][am] = av.y;
        As[ak + 2][am] = av.z; As[ak + 3][am] = av.w;
        *(float4*)&Bs[bk][bc] = *(const float4*)&Bm[(size_t)(k0 + bk) * ldb + n0 + bc];
        __syncthreads();
#pragma unroll
        for (int k = 0; k < 8; k++) {
            float4 a0 = *(float4*)&As[k][ty * 4];
            float4 a1 = *(float4*)&As[k][64 + ty * 4];
            float4 b0 = *(float4*)&Bs[k][tx * 4];
            float4 b1 = *(float4*)&Bs[k][64 + tx * 4];
            float a[8] = {a0.x, a0.y, a0.z, a0.w, a1.x, a1.y, a1.z, a1.w};
            float b[8] = {b0.x, b0.y, b0.z, b0.w, b1.x, b1.y, b1.z, b1.w};
#pragma unroll
            for (int i = 0; i < 8; i++)
#pragma unroll
                for (int j = 0; j < 8; j++)
                    acc[i][j] = fmaf(a[i], b[j], acc[i][j]);
        }
        __syncthreads();
    }

#pragma unroll
    for (int ih = 0; ih < 2; ih++)
#pragma unroll
        for (int di = 0; di < 4; di++) {
            int m = m0 + ih * 64 + ty * 4 + di;
#pragma unroll
            for (int jh = 0; jh < 2; jh++) {
                int n = n0 + jh * 64 + tx * 4;
                float4 v;
                v.x = acc[ih * 4 + di][jh * 4 + 0] + bias[n + 0];
                v.y = acc[ih * 4 + di][jh * 4 + 1] + bias[n + 1];
                v.z = acc[ih * 4 + di][jh * 4 + 2] + bias[n + 2];
                v.w = acc[ih * 4 + di][jh * 4 + 3] + bias[n + 3];
                *(float4*)&C[(size_t)m * ldc + n] = v;
            }
        }
}

// ---------------- params: od = Q @ W_od + b_od, then offsets/durations -----
__device__ __forceinline__ float decode_len(const void* p)
{
    int iv = *(const int*)p;
    if (iv > 0 && iv < (1 << 24)) return (float)iv;   // int32 scalar
    return __int_as_float(iv);                         // float32 scalar
}

__global__ void params_kernel(const float* __restrict__ W_od,
                              const float* __restrict__ b_od,
                              const void*  __restrict__ lenraw)
{
    const int row = blockIdx.x;              // 0..2047
    const int b = row >> 10, t = row & 1023;
    const int tid = threadIdx.x;
    const int w = tid >> 5, lane = tid & 31; // 16 warps, one per od column
    const float* q = g_qkv + (size_t)row * QKVLD;  // Q slice = first E cols

    float s = 0.f;
    for (int k = lane; k < E_; k += 32)
        s = fmaf(q[k], W_od[k * (2 * NH_) + w], s);
#pragma unroll
    for (int o = 16; o; o >>= 1) s += __shfl_xor_sync(0xffffffffu, s, o);

    __shared__ float od[2 * NH_];
    if (lane == 0) od[w] = s + b_od[w];
    __syncthreads();

    if (tid < NH_) {
        const int h = tid;
        const float len = decode_len(lenraw);
        float off = tanhf(od[h]) * len;
        float dur = (1.f / (1.f + expf(-od[NH_ + h]))) * len;
        float anchor = (float)t + off;
        float start = anchor - dur;
        float end   = anchor + dur;
        float bl = floorf(start);
        float br = ceilf(end);
        float al = floorf(anchor);
        float dist = anchor - al;
        int g = b * NH_ + h;
        float* p = g_params + (size_t)(g * T_ + t) * 6;
        p[0] = bl; p[1] = br; p[2] = al; p[3] = dist;
        p[4] = bl - start; p[5] = end - br;
    }
}

// ---------------- fused flash attention -----------------------------------
// One block per (i-tile of 128 queries, head g). Online softmax, point-weight
// + mask fused into the S epilogue. O accumulated in registers over 8 r-tiles.
#define PSLD 132   // padded row length for Ps (128 + 4)

__global__ __launch_bounds__(256, 1) void flash_kernel()
{
    extern __shared__ float sm[];
    float* Qs = sm;                 // [64][128]  k-major, pre-scaled Q
    float* Ks = Qs + 64 * 128;      // [64][128]  k-major
    float* Vs = Ks + 64 * 128;      // [128][64]  r-major
    float* Ps = Vs + 128 * 64;      // [128][PSLD]
    float* pp = Ps + 128 * PSLD;    // [128][6] per-query params

    const int g = blockIdx.y, b = g >> 3, h = g & 7;
    const int i0 = blockIdx.x * 128;
    const int tid = threadIdx.x;
    const int tx = tid & 15, ty = tid >> 4;

    const float* Qg = g_qkv + (size_t)(b * T_) * QKVLD + h * HD_;
    const float* Kg = g_qkv + (size_t)(b * T_) * QKVLD + E_ + h * HD_;
    const float* Vg = g_qkv + (size_t)(b * T_) * QKVLD + 2 * E_ + h * HD_;

    // ---- stage Q (k-major, scaled by 1/8) and params ----
    {
        const int qi = tid >> 1, kh = (tid & 1) * 32;
#pragma unroll
        for (int j = 0; j < 8; j++) {
            float4 v = *(const float4*)&Qg[(size_t)(i0 + qi) * QKVLD + kh + j * 4];
            Qs[(kh + j * 4 + 0) * 128 + qi] = v.x * 0.125f;
            Qs[(kh + j * 4 + 1) * 128 + qi] = v.y * 0.125f;
            Qs[(kh + j * 4 + 2) * 128 + qi] = v.z * 0.125f;
            Qs[(kh + j * 4 + 3) * 128 + qi] = v.w * 0.125f;
        }
        for (int idx = tid; idx < 128 * 6; idx += 256)
            pp[idx] = g_params[(size_t)(g * T_ + i0) * 6 + idx];
    }

    float oa[8][4];
    float mrun[8], lrun[8];
#pragma unroll
    for (int q = 0; q < 8; q++) {
        mrun[q] = -INFINITY; lrun[q] = 0.f;
#pragma unroll
        for (int c = 0; c < 4; c++) oa[q][c] = 0.f;
    }

    const int rrow = tid >> 1, rkh = (tid & 1) * 32;

    for (int it = 0; it < T_ / 128; it++) {
        const int r0 = it * 128;

        // prefetch K, V tile into registers (overlaps prior O-gemm of others)
        float4 kreg[8], vreg[8];
#pragma unroll
        for (int j = 0; j < 8; j++) {
            kreg[j] = *(const float4*)&Kg[(size_t)(r0 + rrow) * QKVLD + rkh + j * 4];
            vreg[j] = *(const float4*)&Vg[(size_t)(r0 + rrow) * QKVLD + rkh + j * 4];
        }
        __syncthreads();   // everyone done reading old Ks/Vs
#pragma unroll
        for (int j = 0; j < 8; j++) {
            Ks[(rkh + j * 4 + 0) * 128 + rrow] = kreg[j].x;
            Ks[(rkh + j * 4 + 1) * 128 + rrow] = kreg[j].y;
            Ks[(rkh + j * 4 + 2) * 128 + rrow] = kreg[j].z;
            Ks[(rkh + j * 4 + 3) * 128 + rrow] = kreg[j].w;
            *(float4*)&Vs[rrow * 64 + rkh + j * 4] = vreg[j];
        }
        __syncthreads();

        // ---- S = Qs^T * Ks  (128x128, acc in regs) ----
        float sa[8][8];
#pragma unroll
        for (int i = 0; i < 8; i++)
#pragma unroll
            for (int j = 0; j < 8; j++) sa[i][j] = 0.f;

#pragma unroll 8
        for (int k = 0; k < 64; k++) {
            float4 a0 = *(float4*)&Qs[k * 128 + ty * 4];
            float4 a1 = *(float4*)&Qs[k * 128 + 64 + ty * 4];
            float4 b0 = *(float4*)&Ks[k * 128 + tx * 4];
            float4 b1 = *(float4*)&Ks[k * 128 + 64 + tx * 4];
            float a[8] = {a0.x, a0.y, a0.z, a0.w, a1.x, a1.y, a1.z, a1.w};
            float bb[8] = {b0.x, b0.y, b0.z, b0.w, b1.x, b1.y, b1.z, b1.w};
#pragma unroll
            for (int i = 0; i < 8; i++)
#pragma unroll
                for (int j = 0; j < 8; j++)
                    sa[i][j] = fmaf(a[i], bb[j], sa[i][j]);
        }

        // ---- epilogue: point-weight, mask, online softmax, P -> Ps ----
#pragma unroll
        for (int ih = 0; ih < 2; ih++)
#pragma unroll
            for (int di = 0; di < 4; di++) {
                const int q = ih * 4 + di;
                const int il = ih * 64 + ty * 4 + di;
                const float bl = pp[il * 6 + 0], br = pp[il * 6 + 1];
                const float al = pp[il * 6 + 2], dist = pp[il * 6 + 3];
                const float wl = pp[il * 6 + 4], wr = pp[il * 6 + 5];

                float rowm = -INFINITY;
#pragma unroll
                for (int jh = 0; jh < 2; jh++)
#pragma unroll
                    for (int dj = 0; dj < 4; dj++) {
                        const float rf = (float)(r0 + jh * 64 + tx * 4 + dj);
                        float s = sa[q][jh * 4 + dj];
                        float w = 1.f;
                        if (rf == bl)       w += wl;
                        if (rf == br)       w += wr;
                        if (rf == al + 1.f) w += dist;
                        if (rf == al)       w += 1.f - dist;
                        s *= w;
                        if (rf < bl || rf > br) s = -1e8f;
                        sa[q][jh * 4 + dj] = s;
                        rowm = fmaxf(rowm, s);
                    }
#pragma unroll
                for (int o = 8; o; o >>= 1)
                    rowm = fmaxf(rowm, __shfl_xor_sync(0xffffffffu, rowm, o));

                const float mnew = fmaxf(mrun[q], rowm);
                const float alpha = __expf(mrun[q] - mnew);
                mrun[q] = mnew;

                float rsum = 0.f;
#pragma unroll
                for (int j = 0; j < 8; j++) {
                    float p = __expf(sa[q][j] - mnew);
                    sa[q][j] = p;
                    rsum += p;
                }
#pragma unroll
                for (int o = 8; o; o >>= 1)
                    rsum += __shfl_xor_sync(0xffffffffu, rsum, o);
                lrun[q] = lrun[q] * alpha + rsum;

#pragma unroll
                for (int c = 0; c < 4; c++) oa[q][c] *= alpha;

                *(float4*)&Ps[il * PSLD + tx * 4]       = *(float4*)&sa[q][0];
                *(float4*)&Ps[il * PSLD + 64 + tx * 4]  = *(float4*)&sa[q][4];
            }
        __syncthreads();

        // ---- O += P @ V ----
        const float* prow[8];
#pragma unroll
        for (int ih = 0; ih < 2; ih++)
#pragma unroll
            for (int di = 0; di < 4; di++)
                prow[ih * 4 + di] = Ps + (ih * 64 + ty * 4 + di) * PSLD;

#pragma unroll 4
        for (int r = 0; r < 128; r += 2) {
            float4 bv0 = *(float4*)&Vs[r * 64 + tx * 4];
            float4 bv1 = *(float4*)&Vs[(r + 1) * 64 + tx * 4];
#pragma unroll
            for (int q = 0; q < 8; q++) {
                float2 av = *(const float2*)(prow[q] + r);
                oa[q][0] = fmaf(av.x, bv0.x, oa[q][0]);
                oa[q][1] = fmaf(av.x, bv0.y, oa[q][1]);
                oa[q][2] = fmaf(av.x, bv0.z, oa[q][2]);
                oa[q][3] = fmaf(av.x, bv0.w, oa[q][3]);
                oa[q][0] = fmaf(av.y, bv1.x, oa[q][0]);
                oa[q][1] = fmaf(av.y, bv1.y, oa[q][1]);
                oa[q][2] = fmaf(av.y, bv1.z, oa[q][2]);
                oa[q][3] = fmaf(av.y, bv1.w, oa[q][3]);
            }
        }
    }

    // ---- normalize and write out (b, t, e) ----
    float* O = g_attnout + (size_t)(b * T_) * E_ + h * HD_;
#pragma unroll
    for (int ih = 0; ih < 2; ih++)
#pragma unroll
        for (int di = 0; di < 4; di++) {
            const int q = ih * 4 + di;
            const int i = i0 + ih * 64 + ty * 4 + di;
            const float inv = 1.f / lrun[q];
            float4 v;
            v.x = oa[q][0] * inv; v.y = oa[q][1] * inv;
            v.z = oa[q][2] * inv; v.w = oa[q][3] * inv;
            *(float4*)&O[(size_t)i * E_ + tx * 4] = v;
        }
}

// ---------------- host launch ----------------------------------------------
extern "C" void kernel_launch(void* const* d_in, const int* in_sizes, int n_in,
                              void* d_out, int out_size)
{
    const float* x      = (const float*)d_in[0];
    const float* W_qkv  = (const float*)d_in[1];
    const float* b_qkv  = (const float*)d_in[2];
    const float* W_od   = (const float*)d_in[3];
    const float* b_od   = (const float*)d_in[4];
    const float* W_out  = (const float*)d_in[5];
    const float* b_out  = (const float*)d_in[6];
    const void*  lenp   = (const void*)d_in[7];
    float* out = (float*)d_out;

    static float* qkv_p = nullptr;
    static float* attnout_p = nullptr;
    static bool configured = false;
    const int FLASH_SMEM = (64 * 128 * 2 + 128 * 64 + 128 * PSLD + 128 * 6) * 4;
    if (!configured) {
        cudaGetSymbolAddress((void**)&qkv_p, g_qkv);
        cudaGetSymbolAddress((void**)&attnout_p, g_attnout);
        cudaFuncSetAttribute(flash_kernel,
                             cudaFuncAttributeMaxDynamicSharedMemorySize,
                             FLASH_SMEM);
        configured = true;
    }

    // 1) qkv = x @ W_qkv + b_qkv       (2048 x 1536 x 512)
    sgemm_bias_128<<<dim3(QKVLD / 128, (B_ * T_) / 128), 256>>>(
        B_ * T_, QKVLD, E_, x, E_, W_qkv, QKVLD, b_qkv, qkv_p, QKVLD);

    // 2) od projection + per-(head,query) band parameters
    params_kernel<<<B_ * T_, 512>>>(W_od, b_od, lenp);

    // 3) fused attention: scores + point-weight + mask + softmax + @V
    flash_kernel<<<dim3(T_ / 128, BNH_), 256, FLASH_SMEM>>>();

    // 4) result = attn_out @ W_out + b_out   (2048 x 512 x 512)
    sgemm_bias_128<<<dim3(E_ / 128, (B_ * T_) / 128), 256>>>(
        B_ * T_, E_, E_, attnout_p, E_, W_out, E_, b_out, out, E_);
}

// round 7
// speedup vs baseline: 1.4212x; 1.1859x over previous
#include <cuda_runtime.h>
#include <math.h>

#define B_   2
#define T_   1024
#define E_   512
#define NH_  8
#define HD_  64
#define BNH_ 16
#define QKVLD (3*E_)   // 1536

// ---------------- scratch (device globals: allocation-free) ----------------
__device__ float g_qkv[B_*T_*3*E_];          // (2048, 1536) rows = b*T+t
__device__ float g_params[BNH_*T_*6];        // per (g,t): bl, br, al, dist, bl-start, end-br
__device__ float g_attnout[B_*T_*E_];        // (2048, 512)

// ---------------- SGEMM + bias: 128x64 tile, 8x4 microtile, reg prefetch ---
// 256 threads. Grid (N/64, M/128). Designed for 2-3 CTAs/SM residency.
__global__ __launch_bounds__(256) void sgemm_bias_128x64(
    int K,
    const float* __restrict__ A, int lda,
    const float* __restrict__ Bm, int ldb,
    const float* __restrict__ bias,
    float* __restrict__ C, int ldc)
{
    __shared__ float As[8][128];
    __shared__ float Bs[8][64];
    const int tid = threadIdx.x;
    const int tx = tid & 15, ty = tid >> 4;
    const int m0 = blockIdx.y * 128, n0 = blockIdx.x * 64;

    // load assignments
    const int am = tid >> 1, ak = (tid & 1) * 4;      // A: 128 rows x 8 k (float4 along k)
    const int bk = tid >> 5, bc = (tid & 31) * 2;     // B: 8 k-rows x 64 n (float2 along n)

    const float* Aptr = A + (size_t)(m0 + am) * lda + ak;
    const float* Bptr = Bm + (size_t)bk * ldb + n0 + bc;

    // prefetch first tile into registers
    float4 areg = *(const float4*)Aptr;
    float2 breg = *(const float2*)Bptr;

    float acc[8][4];
#pragma unroll
    for (int i = 0; i < 8; i++)
#pragma unroll
        for (int j = 0; j < 4; j++) acc[i][j] = 0.f;

    for (int k0 = 0; k0 < K; k0 += 8) {
        // stage current tile to smem
        As[ak + 0][am] = areg.x; As[ak + 1][am] = areg.y;
        As[ak + 2][am] = areg.z; As[ak + 3][am] = areg.w;
        *(float2*)&Bs[bk][bc] = breg;
        __syncthreads();

        // issue next tile's global loads early (latency hides under FFMAs)
        if (k0 + 8 < K) {
            areg = *(const float4*)(Aptr + k0 + 8);
            breg = *(const float2*)(Bptr + (size_t)(k0 + 8) * ldb);
        }

#pragma unroll
        for (int k = 0; k < 8; k++) {
            float4 a0 = *(float4*)&As[k][ty * 4];
            float4 a1 = *(float4*)&As[k][64 + ty * 4];
            float4 bv = *(float4*)&Bs[k][tx * 4];
            float a[8] = {a0.x, a0.y, a0.z, a0.w, a1.x, a1.y, a1.z, a1.w};
#pragma unroll
            for (int i = 0; i < 8; i++) {
                acc[i][0] = fmaf(a[i], bv.x, acc[i][0]);
                acc[i][1] = fmaf(a[i], bv.y, acc[i][1]);
                acc[i][2] = fmaf(a[i], bv.z, acc[i][2]);
                acc[i][3] = fmaf(a[i], bv.w, acc[i][3]);
            }
        }
        __syncthreads();
    }

    const int n = n0 + tx * 4;
    const float4 bz = *(const float4*)&bias[n];
#pragma unroll
    for (int ih = 0; ih < 2; ih++)
#pragma unroll
        for (int di = 0; di < 4; di++) {
            const int i = ih * 4 + di;
            const int m = m0 + ih * 64 + ty * 4 + di;
            float4 v;
            v.x = acc[i][0] + bz.x; v.y = acc[i][1] + bz.y;
            v.z = acc[i][2] + bz.z; v.w = acc[i][3] + bz.w;
            *(float4*)&C[(size_t)m * ldc + n] = v;
        }
}

// ---------------- params: od = Q @ W_od + b_od, then offsets/durations -----
__device__ __forceinline__ float decode_len(const void* p)
{
    int iv = *(const int*)p;
    if (iv > 0 && iv < (1 << 24)) return (float)iv;   // int32 scalar
    return __int_as_float(iv);                         // float32 scalar
}

__global__ void params_kernel(const float* __restrict__ W_od,
                              const float* __restrict__ b_od,
                              const void*  __restrict__ lenraw)
{
    const int row = blockIdx.x;              // 0..2047
    const int b = row >> 10, t = row & 1023;
    const int tid = threadIdx.x;
    const int w = tid >> 5, lane = tid & 31; // 16 warps, one per od column
    const float* q = g_qkv + (size_t)row * QKVLD;  // Q slice = first E cols

    float s = 0.f;
    for (int k = lane; k < E_; k += 32)
        s = fmaf(q[k], W_od[k * (2 * NH_) + w], s);
#pragma unroll
    for (int o = 16; o; o >>= 1) s += __shfl_xor_sync(0xffffffffu, s, o);

    __shared__ float od[2 * NH_];
    if (lane == 0) od[w] = s + b_od[w];
    __syncthreads();

    if (tid < NH_) {
        const int h = tid;
        const float len = decode_len(lenraw);
        float off = tanhf(od[h]) * len;
        float dur = (1.f / (1.f + expf(-od[NH_ + h]))) * len;
        float anchor = (float)t + off;
        float start = anchor - dur;
        float end   = anchor + dur;
        float bl = floorf(start);
        float br = ceilf(end);
        float al = floorf(anchor);
        float dist = anchor - al;
        int g = b * NH_ + h;
        float* p = g_params + (size_t)(g * T_ + t) * 6;
        p[0] = bl; p[1] = br; p[2] = al; p[3] = dist;
        p[4] = bl - start; p[5] = end - br;
    }
}

// ---------------- fused flash attention -----------------------------------
// One block per (i-tile of 128 queries, head g). Online softmax, point-weight
// + mask fused into the S epilogue. O accumulated in registers over 8 r-tiles.
#define PSLD 132   // padded row length for Ps (128 + 4)

__global__ __launch_bounds__(256, 1) void flash_kernel()
{
    extern __shared__ float sm[];
    float* Qs = sm;                 // [64][128]  k-major, pre-scaled Q
    float* Ks = Qs + 64 * 128;      // [64][128]  k-major
    float* Vs = Ks + 64 * 128;      // [128][64]  r-major
    float* Ps = Vs + 128 * 64;      // [128][PSLD]
    float* pp = Ps + 128 * PSLD;    // [128][6] per-query params

    const int g = blockIdx.y, b = g >> 3, h = g & 7;
    const int i0 = blockIdx.x * 128;
    const int tid = threadIdx.x;
    const int tx = tid & 15, ty = tid >> 4;

    const float* Qg = g_qkv + (size_t)(b * T_) * QKVLD + h * HD_;
    const float* Kg = g_qkv + (size_t)(b * T_) * QKVLD + E_ + h * HD_;
    const float* Vg = g_qkv + (size_t)(b * T_) * QKVLD + 2 * E_ + h * HD_;

    // ---- stage Q (k-major, scaled by 1/8) and params ----
    {
        const int qi = tid >> 1, kh = (tid & 1) * 32;
#pragma unroll
        for (int j = 0; j < 8; j++) {
            float4 v = *(const float4*)&Qg[(size_t)(i0 + qi) * QKVLD + kh + j * 4];
            Qs[(kh + j * 4 + 0) * 128 + qi] = v.x * 0.125f;
            Qs[(kh + j * 4 + 1) * 128 + qi] = v.y * 0.125f;
            Qs[(kh + j * 4 + 2) * 128 + qi] = v.z * 0.125f;
            Qs[(kh + j * 4 + 3) * 128 + qi] = v.w * 0.125f;
        }
        for (int idx = tid; idx < 128 * 6; idx += 256)
            pp[idx] = g_params[(size_t)(g * T_ + i0) * 6 + idx];
    }

    float oa[8][4];
    float mrun[8], lrun[8];
#pragma unroll
    for (int q = 0; q < 8; q++) {
        mrun[q] = -INFINITY; lrun[q] = 0.f;
#pragma unroll
        for (int c = 0; c < 4; c++) oa[q][c] = 0.f;
    }

    const int rrow = tid >> 1, rkh = (tid & 1) * 32;

    for (int it = 0; it < T_ / 128; it++) {
        const int r0 = it * 128;

        // prefetch K, V tile into registers (overlaps prior O-gemm of others)
        float4 kreg[8], vreg[8];
#pragma unroll
        for (int j = 0; j < 8; j++) {
            kreg[j] = *(const float4*)&Kg[(size_t)(r0 + rrow) * QKVLD + rkh + j * 4];
            vreg[j] = *(const float4*)&Vg[(size_t)(r0 + rrow) * QKVLD + rkh + j * 4];
        }
        __syncthreads();   // everyone done reading old Ks/Vs
#pragma unroll
        for (int j = 0; j < 8; j++) {
            Ks[(rkh + j * 4 + 0) * 128 + rrow] = kreg[j].x;
            Ks[(rkh + j * 4 + 1) * 128 + rrow] = kreg[j].y;
            Ks[(rkh + j * 4 + 2) * 128 + rrow] = kreg[j].z;
            Ks[(rkh + j * 4 + 3) * 128 + rrow] = kreg[j].w;
            *(float4*)&Vs[rrow * 64 + rkh + j * 4] = vreg[j];
        }
        __syncthreads();

        // ---- S = Qs^T * Ks  (128x128, acc in regs) ----
        float sa[8][8];
#pragma unroll
        for (int i = 0; i < 8; i++)
#pragma unroll
            for (int j = 0; j < 8; j++) sa[i][j] = 0.f;

#pragma unroll 8
        for (int k = 0; k < 64; k++) {
            float4 a0 = *(float4*)&Qs[k * 128 + ty * 4];
            float4 a1 = *(float4*)&Qs[k * 128 + 64 + ty * 4];
            float4 b0 = *(float4*)&Ks[k * 128 + tx * 4];
            float4 b1 = *(float4*)&Ks[k * 128 + 64 + tx * 4];
            float a[8] = {a0.x, a0.y, a0.z, a0.w, a1.x, a1.y, a1.z, a1.w};
            float bb[8] = {b0.x, b0.y, b0.z, b0.w, b1.x, b1.y, b1.z, b1.w};
#pragma unroll
            for (int i = 0; i < 8; i++)
#pragma unroll
                for (int j = 0; j < 8; j++)
                    sa[i][j] = fmaf(a[i], bb[j], sa[i][j]);
        }

        // ---- epilogue: point-weight, mask, online softmax, P -> Ps ----
#pragma unroll
        for (int ih = 0; ih < 2; ih++)
#pragma unroll
            for (int di = 0; di < 4; di++) {
                const int q = ih * 4 + di;
                const int il = ih * 64 + ty * 4 + di;
                const float bl = pp[il * 6 + 0], br = pp[il * 6 + 1];
                const float al = pp[il * 6 + 2], dist = pp[il * 6 + 3];
                const float wl = pp[il * 6 + 4], wr = pp[il * 6 + 5];

                float rowm = -INFINITY;
#pragma unroll
                for (int jh = 0; jh < 2; jh++)
#pragma unroll
                    for (int dj = 0; dj < 4; dj++) {
                        const float rf = (float)(r0 + jh * 64 + tx * 4 + dj);
                        float s = sa[q][jh * 4 + dj];
                        float w = 1.f;
                        if (rf == bl)       w += wl;
                        if (rf == br)       w += wr;
                        if (rf == al + 1.f) w += dist;
                        if (rf == al)       w += 1.f - dist;
                        s *= w;
                        if (rf < bl || rf > br) s = -1e8f;
                        sa[q][jh * 4 + dj] = s;
                        rowm = fmaxf(rowm, s);
                    }
#pragma unroll
                for (int o = 8; o; o >>= 1)
                    rowm = fmaxf(rowm, __shfl_xor_sync(0xffffffffu, rowm, o));

                const float mnew = fmaxf(mrun[q], rowm);
                const float alpha = __expf(mrun[q] - mnew);
                mrun[q] = mnew;

                float rsum = 0.f;
#pragma unroll
                for (int j = 0; j < 8; j++) {
                    float p = __expf(sa[q][j] - mnew);
                    sa[q][j] = p;
                    rsum += p;
                }
#pragma unroll
                for (int o = 8; o; o >>= 1)
                    rsum += __shfl_xor_sync(0xffffffffu, rsum, o);
                lrun[q] = lrun[q] * alpha + rsum;

#pragma unroll
                for (int c = 0; c < 4; c++) oa[q][c] *= alpha;

                *(float4*)&Ps[il * PSLD + tx * 4]       = *(float4*)&sa[q][0];
                *(float4*)&Ps[il * PSLD + 64 + tx * 4]  = *(float4*)&sa[q][4];
            }
        __syncthreads();

        // ---- O += P @ V ----
        const float* prow[8];
#pragma unroll
        for (int ih = 0; ih < 2; ih++)
#pragma unroll
            for (int di = 0; di < 4; di++)
                prow[ih * 4 + di] = Ps + (ih * 64 + ty * 4 + di) * PSLD;

#pragma unroll 4
        for (int r = 0; r < 128; r += 2) {
            float4 bv0 = *(float4*)&Vs[r * 64 + tx * 4];
            float4 bv1 = *(float4*)&Vs[(r + 1) * 64 + tx * 4];
#pragma unroll
            for (int q = 0; q < 8; q++) {
                float2 av = *(const float2*)(prow[q] + r);
                oa[q][0] = fmaf(av.x, bv0.x, oa[q][0]);
                oa[q][1] = fmaf(av.x, bv0.y, oa[q][1]);
                oa[q][2] = fmaf(av.x, bv0.z, oa[q][2]);
                oa[q][3] = fmaf(av.x, bv0.w, oa[q][3]);
                oa[q][0] = fmaf(av.y, bv1.x, oa[q][0]);
                oa[q][1] = fmaf(av.y, bv1.y, oa[q][1]);
                oa[q][2] = fmaf(av.y, bv1.z, oa[q][2]);
                oa[q][3] = fmaf(av.y, bv1.w, oa[q][3]);
            }
        }
    }

    // ---- normalize and write out (b, t, e) ----
    float* O = g_attnout + (size_t)(b * T_) * E_ + h * HD_;
#pragma unroll
    for (int ih = 0; ih < 2; ih++)
#pragma unroll
        for (int di = 0; di < 4; di++) {
            const int q = ih * 4 + di;
            const int i = i0 + ih * 64 + ty * 4 + di;
            const float inv = 1.f / lrun[q];
            float4 v;
            v.x = oa[q][0] * inv; v.y = oa[q][1] * inv;
            v.z = oa[q][2] * inv; v.w = oa[q][3] * inv;
            *(float4*)&O[(size_t)i * E_ + tx * 4] = v;
        }
}

// ---------------- host launch ----------------------------------------------
extern "C" void kernel_launch(void* const* d_in, const int* in_sizes, int n_in,
                              void* d_out, int out_size)
{
    const float* x      = (const float*)d_in[0];
    const float* W_qkv  = (const float*)d_in[1];
    const float* b_qkv  = (const float*)d_in[2];
    const float* W_od   = (const float*)d_in[3];
    const float* b_od   = (const float*)d_in[4];
    const float* W_out  = (const float*)d_in[5];
    const float* b_out  = (const float*)d_in[6];
    const void*  lenp   = (const void*)d_in[7];
    float* out = (float*)d_out;

    static float* qkv_p = nullptr;
    static float* attnout_p = nullptr;
    static bool configured = false;
    const int FLASH_SMEM = (64 * 128 * 2 + 128 * 64 + 128 * PSLD + 128 * 6) * 4;
    if (!configured) {
        cudaGetSymbolAddress((void**)&qkv_p, g_qkv);
        cudaGetSymbolAddress((void**)&attnout_p, g_attnout);
        cudaFuncSetAttribute(flash_kernel,
                             cudaFuncAttributeMaxDynamicSharedMemorySize,
                             FLASH_SMEM);
        configured = true;
    }

    // 1) qkv = x @ W_qkv + b_qkv       (2048 x 1536 x 512), grid 24x16=384
    sgemm_bias_128x64<<<dim3(QKVLD / 64, (B_ * T_) / 128), 256>>>(
        E_, x, E_, W_qkv, QKVLD, b_qkv, qkv_p, QKVLD);

    // 2) od projection + per-(head,query) band parameters
    params_kernel<<<B_ * T_, 512>>>(W_od, b_od, lenp);

    // 3) fused attention: scores + point-weight + mask + softmax + @V
    flash_kernel<<<dim3(T_ / 128, BNH_), 256, FLASH_SMEM>>>();

    // 4) result = attn_out @ W_out + b_out   (2048 x 512 x 512), grid 8x16=128
    sgemm_bias_128x64<<<dim3(E_ / 64, (B_ * T_) / 128), 256>>>(
        E_, attnout_p, E_, W_out, E_, b_out, out, E_);
}

// round 15
// speedup vs baseline: 1.5974x; 1.1240x over previous
#include <cuda_runtime.h>
#include <cuda_bf16.h>
#include <math.h>
#include <stdint.h>

#define B_   2
#define T_   1024
#define E_   512
#define NH_  8
#define HD_  64
#define BNH_ 16
#define QKVLD (3*E_)   // 1536

// ---------------- scratch (device globals: allocation-free) ----------------
__device__ float g_qkv[B_*T_*3*E_];          // (2048, 1536) rows = b*T+t
__device__ float g_params[BNH_*T_*6];        // per (g,t): bl, br, al, dist, bl-start, end-br
__device__ float g_attnout[B_*T_*E_];        // (2048, 512)
__device__ float g_wc[E_*2*NH_];             // fused od weights: (512, 16)
__device__ float g_bc[2*NH_];                // fused od bias

// ================= portable PTX helpers (base sm_103 target) ===============
__device__ __forceinline__ uint32_t smem_u32(const void* p) {
    uint32_t a;
    asm("{ .reg .u64 t; cvta.to.shared.u64 t, %1; cvt.u32.u64 %0, t; }"
        : "=r"(a) : "l"(p));
    return a;
}
#define SW128(off) ((off) ^ (((off) >> 3) & 0x70))

__device__ __forceinline__ void ldsm4(uint32_t* r, uint32_t a) {
    asm volatile("ldmatrix.sync.aligned.m8n8.x4.shared.b16 {%0,%1,%2,%3}, [%4];"
                 : "=r"(r[0]), "=r"(r[1]), "=r"(r[2]), "=r"(r[3]) : "r"(a));
}
__device__ __forceinline__ void mma_bf16(float* d, const uint32_t* a,
                                         uint32_t b0, uint32_t b1) {
    asm volatile(
        "mma.sync.aligned.m16n8k16.row.col.f32.bf16.bf16.f32 "
        "{%0,%1,%2,%3}, {%4,%5,%6,%7}, {%8,%9}, {%0,%1,%2,%3};"
        : "+f"(d[0]), "+f"(d[1]), "+f"(d[2]), "+f"(d[3])
        : "r"(a[0]), "r"(a[1]), "r"(a[2]), "r"(a[3]), "r"(b0), "r"(b1));
}

// ============ mma.sync GEMM + bias: C[M,N] = A[M,K] @ B[K,N] + bias ========
// fp32 via bf16 3-term split. CTA tile 128x64, 8 warps (4x2), warp tile 32x32.
// K chunks of 64. grid = (N/64, M/128). 256 threads.
#define GA_H 0
#define GA_L 16384
#define GB_H 32768
#define GB_L 40960
#define GSMEM 49152

__global__ __launch_bounds__(256) void gemm_mma(
    int K,
    const float* __restrict__ A, int lda,
    const float* __restrict__ Bm, int ldb,
    const float* __restrict__ bias,
    float* __restrict__ C, int ldc)
{
    extern __shared__ char smg[];
    const uint32_t sb = smem_u32(smg);
    const int tid = threadIdx.x, wid = tid >> 5, lane = tid & 31;
    const int m0 = blockIdx.y * 128, n0 = blockIdx.x * 64;
    const int wm = (wid & 3) * 32, wn = (wid >> 2) * 32;
    const int lrow = lane & 15, lu = lane >> 4;

    float acc[2][4][4];
#pragma unroll
    for (int mi = 0; mi < 2; mi++)
#pragma unroll
        for (int nj = 0; nj < 4; nj++)
#pragma unroll
            for (int e = 0; e < 4; e++) acc[mi][nj][e] = 0.f;

    for (int k0 = 0; k0 < K; k0 += 64) {
        // ---- stage A chunk: 128 rows x 64 k -> bf16 hi/lo, SW128 ----
#pragma unroll
        for (int i = 0; i < 8; i++) {
            const int gid = i * 256 + tid;
            const int m = gid >> 4, k4 = gid & 15;
            float4 av = *(const float4*)&A[(size_t)(m0 + m) * lda + k0 + k4 * 4];
            __nv_bfloat162 h01 = __floats2bfloat162_rn(av.x, av.y);
            __nv_bfloat162 h23 = __floats2bfloat162_rn(av.z, av.w);
            float2 f01 = __bfloat1622float2(h01);
            float2 f23 = __bfloat1622float2(h23);
            __nv_bfloat162 l01 = __floats2bfloat162_rn(av.x - f01.x, av.y - f01.y);
            __nv_bfloat162 l23 = __floats2bfloat162_rn(av.z - f23.x, av.w - f23.y);
            const uint32_t so = SW128((uint32_t)(m * 128 + k4 * 8));
            *(uint2*)(smg + GA_H + so) = make_uint2(*(uint32_t*)&h01, *(uint32_t*)&h23);
            *(uint2*)(smg + GA_L + so) = make_uint2(*(uint32_t*)&l01, *(uint32_t*)&l23);
        }
        // ---- stage B chunk: B[K,N] -> Bs[n][k] (transpose), hi/lo ----
#pragma unroll
        for (int i = 0; i < 4; i++) {
            const int gid = i * 256 + tid;
            const int n = gid & 63, k4 = gid >> 6;
            const float* bp = &Bm[(size_t)(k0 + k4 * 4) * ldb + n0 + n];
            float f0 = bp[0];
            float f1 = bp[ldb];
            float f2 = bp[2 * (size_t)ldb];
            float f3 = bp[3 * (size_t)ldb];
            __nv_bfloat162 h01 = __floats2bfloat162_rn(f0, f1);
            __nv_bfloat162 h23 = __floats2bfloat162_rn(f2, f3);
            float2 q01 = __bfloat1622float2(h01);
            float2 q23 = __bfloat1622float2(h23);
            __nv_bfloat162 l01 = __floats2bfloat162_rn(f0 - q01.x, f1 - q01.y);
            __nv_bfloat162 l23 = __floats2bfloat162_rn(f2 - q23.x, f3 - q23.y);
            const uint32_t so = SW128((uint32_t)(n * 128 + k4 * 8));
            *(uint2*)(smg + GB_H + so) = make_uint2(*(uint32_t*)&h01, *(uint32_t*)&h23);
            *(uint2*)(smg + GB_L + so) = make_uint2(*(uint32_t*)&l01, *(uint32_t*)&l23);
        }
        __syncthreads();

        // ---- compute: 4 k16 steps ----
#pragma unroll
        for (int ks = 0; ks < 4; ks++) {
            const uint32_t uoff = (2 * ks + lu) * 16;
            uint32_t ah[2][4], al[2][4];
#pragma unroll
            for (int mi = 0; mi < 2; mi++) {
                const uint32_t off = SW128((uint32_t)((wm + mi * 16 + lrow) * 128) + uoff);
                ldsm4(ah[mi], sb + GA_H + off);
                ldsm4(al[mi], sb + GA_L + off);
            }
            uint32_t bh[2][4], bl[2][4];
#pragma unroll
            for (int nj2 = 0; nj2 < 2; nj2++) {
                const uint32_t off = SW128((uint32_t)((wn + nj2 * 16 + lrow) * 128) + uoff);
                ldsm4(bh[nj2], sb + GB_H + off);
                ldsm4(bl[nj2], sb + GB_L + off);
            }
#pragma unroll
            for (int mi = 0; mi < 2; mi++)
#pragma unroll
                for (int nj2 = 0; nj2 < 2; nj2++)
#pragma unroll
                    for (int hf = 0; hf < 2; hf++) {
                        float* d = acc[mi][nj2 * 2 + hf];
                        mma_bf16(d, ah[mi], bh[nj2][hf], bh[nj2][hf + 2]);
                        mma_bf16(d, ah[mi], bl[nj2][hf], bl[nj2][hf + 2]);
                        mma_bf16(d, al[mi], bh[nj2][hf], bh[nj2][hf + 2]);
                    }
        }
        __syncthreads();
    }

    // ---- epilogue: frag layout c0,c1 -> (row g, col 2t), c2,c3 -> row g+8 ---
    const int g2 = lane >> 2, t2 = (lane & 3) * 2;
#pragma unroll
    for (int mi = 0; mi < 2; mi++)
#pragma unroll
        for (int nj = 0; nj < 4; nj++) {
            const int m = m0 + wm + mi * 16 + g2;
            const int n = n0 + wn + nj * 8 + t2;
            const float b0 = __ldg(&bias[n]), b1 = __ldg(&bias[n + 1]);
            float2 v0 = make_float2(acc[mi][nj][0] + b0, acc[mi][nj][1] + b1);
            float2 v1 = make_float2(acc[mi][nj][2] + b0, acc[mi][nj][3] + b1);
            *(float2*)&C[(size_t)m * ldc + n] = v0;
            *(float2*)&C[(size_t)(m + 8) * ldc + n] = v1;
        }
}

// ------------ fused od weights: Wc = W_qkv[:, :E] @ W_od ; bc = b_q@W_od+b_od
__global__ __launch_bounds__(512) void wc_kernel(
    const float* __restrict__ W_qkv, const float* __restrict__ b_qkv,
    const float* __restrict__ W_od, const float* __restrict__ b_od)
{
    const int tid = threadIdx.x;
    const int k = blockIdx.x * 32 + (tid >> 4);   // 0..511
    const int w = tid & 15;                        // 0..15
    float s = 0.f;
    for (int j = 0; j < E_; j++)
        s = fmaf(W_qkv[(size_t)k * QKVLD + j], W_od[j * (2 * NH_) + w], s);
    g_wc[k * (2 * NH_) + w] = s;
    if (blockIdx.x == 0 && tid < 2 * NH_) {
        float t = 0.f;
        for (int j = 0; j < E_; j++)
            t = fmaf(b_qkv[j], W_od[j * (2 * NH_) + tid], t);
        g_bc[tid] = t + b_od[tid];
    }
}

// ---------------- params: od = x @ Wc + bc (exact fp32 path) ---------------
__device__ __forceinline__ float decode_len(const void* p)
{
    int iv = *(const int*)p;
    if (iv > 0 && iv < (1 << 24)) return (float)iv;   // int32 scalar
    return __int_as_float(iv);                         // float32 scalar
}

__global__ void params_kernel(const float* __restrict__ x,
                              const void*  __restrict__ lenraw)
{
    const int row = blockIdx.x;              // 0..2047
    const int b = row >> 10, t = row & 1023;
    const int tid = threadIdx.x;
    const int w = tid >> 5, lane = tid & 31; // 16 warps, one per od column
    const float* q = x + (size_t)row * E_;

    float s = 0.f;
    for (int k = lane; k < E_; k += 32)
        s = fmaf(q[k], g_wc[k * (2 * NH_) + w], s);
#pragma unroll
    for (int o = 16; o; o >>= 1) s += __shfl_xor_sync(0xffffffffu, s, o);

    __shared__ float od[2 * NH_];
    if (lane == 0) od[w] = s + g_bc[w];
    __syncthreads();

    if (tid < NH_) {
        const int h = tid;
        const float len = decode_len(lenraw);
        float off = tanhf(od[h]) * len;
        float dur = (1.f / (1.f + expf(-od[NH_ + h]))) * len;
        float anchor = (float)t + off;
        float start = anchor - dur;
        float end   = anchor + dur;
        float bl = floorf(start);
        float br = ceilf(end);
        float al = floorf(anchor);
        float dist = anchor - al;
        int g = b * NH_ + h;
        float* p = g_params + (size_t)(g * T_ + t) * 6;
        p[0] = bl; p[1] = br; p[2] = al; p[3] = dist;
        p[4] = bl - start; p[5] = end - br;
    }
}

// ---------------- fused flash attention (unchanged) ------------------------
#define PSLD 132   // padded row length for Ps (128 + 4)

__global__ __launch_bounds__(256, 1) void flash_kernel()
{
    extern __shared__ float sm[];
    float* Qs = sm;                 // [64][128]  k-major, pre-scaled Q
    float* Ks = Qs + 64 * 128;      // [64][128]  k-major
    float* Vs = Ks + 64 * 128;      // [128][64]  r-major
    float* Ps = Vs + 128 * 64;      // [128][PSLD]
    float* pp = Ps + 128 * PSLD;    // [128][6] per-query params

    const int g = blockIdx.y, b = g >> 3, h = g & 7;
    const int i0 = blockIdx.x * 128;
    const int tid = threadIdx.x;
    const int tx = tid & 15, ty = tid >> 4;

    const float* Qg = g_qkv + (size_t)(b * T_) * QKVLD + h * HD_;
    const float* Kg = g_qkv + (size_t)(b * T_) * QKVLD + E_ + h * HD_;
    const float* Vg = g_qkv + (size_t)(b * T_) * QKVLD + 2 * E_ + h * HD_;

    {
        const int qi = tid >> 1, kh = (tid & 1) * 32;
#pragma unroll
        for (int j = 0; j < 8; j++) {
            float4 v = *(const float4*)&Qg[(size_t)(i0 + qi) * QKVLD + kh + j * 4];
            Qs[(kh + j * 4 + 0) * 128 + qi] = v.x * 0.125f;
            Qs[(kh + j * 4 + 1) * 128 + qi] = v.y * 0.125f;
            Qs[(kh + j * 4 + 2) * 128 + qi] = v.z * 0.125f;
            Qs[(kh + j * 4 + 3) * 128 + qi] = v.w * 0.125f;
        }
        for (int idx = tid; idx < 128 * 6; idx += 256)
            pp[idx] = g_params[(size_t)(g * T_ + i0) * 6 + idx];
    }

    float oa[8][4];
    float mrun[8], lrun[8];
#pragma unroll
    for (int q = 0; q < 8; q++) {
        mrun[q] = -INFINITY; lrun[q] = 0.f;
#pragma unroll
        for (int c = 0; c < 4; c++) oa[q][c] = 0.f;
    }

    const int rrow = tid >> 1, rkh = (tid & 1) * 32;

    for (int it = 0; it < T_ / 128; it++) {
        const int r0 = it * 128;

        float4 kreg[8], vreg[8];
#pragma unroll
        for (int j = 0; j < 8; j++) {
            kreg[j] = *(const float4*)&Kg[(size_t)(r0 + rrow) * QKVLD + rkh + j * 4];
            vreg[j] = *(const float4*)&Vg[(size_t)(r0 + rrow) * QKVLD + rkh + j * 4];
        }
        __syncthreads();
#pragma unroll
        for (int j = 0; j < 8; j++) {
            Ks[(rkh + j * 4 + 0) * 128 + rrow] = kreg[j].x;
            Ks[(rkh + j * 4 + 1) * 128 + rrow] = kreg[j].y;
            Ks[(rkh + j * 4 + 2) * 128 + rrow] = kreg[j].z;
            Ks[(rkh + j * 4 + 3) * 128 + rrow] = kreg[j].w;
            *(float4*)&Vs[rrow * 64 + rkh + j * 4] = vreg[j];
        }
        __syncthreads();

        float sa[8][8];
#pragma unroll
        for (int i = 0; i < 8; i++)
#pragma unroll
            for (int j = 0; j < 8; j++) sa[i][j] = 0.f;

#pragma unroll 8
        for (int k = 0; k < 64; k++) {
            float4 a0 = *(float4*)&Qs[k * 128 + ty * 4];
            float4 a1 = *(float4*)&Qs[k * 128 + 64 + ty * 4];
            float4 b0 = *(float4*)&Ks[k * 128 + tx * 4];
            float4 b1 = *(float4*)&Ks[k * 128 + 64 + tx * 4];
            float a[8] = {a0.x, a0.y, a0.z, a0.w, a1.x, a1.y, a1.z, a1.w};
            float bb[8] = {b0.x, b0.y, b0.z, b0.w, b1.x, b1.y, b1.z, b1.w};
#pragma unroll
            for (int i = 0; i < 8; i++)
#pragma unroll
                for (int j = 0; j < 8; j++)
                    sa[i][j] = fmaf(a[i], bb[j], sa[i][j]);
        }

#pragma unroll
        for (int ih = 0; ih < 2; ih++)
#pragma unroll
            for (int di = 0; di < 4; di++) {
                const int q = ih * 4 + di;
                const int il = ih * 64 + ty * 4 + di;
                const float bl = pp[il * 6 + 0], br = pp[il * 6 + 1];
                const float al = pp[il * 6 + 2], dist = pp[il * 6 + 3];
                const float wl = pp[il * 6 + 4], wr = pp[il * 6 + 5];

                float rowm = -INFINITY;
#pragma unroll
                for (int jh = 0; jh < 2; jh++)
#pragma unroll
                    for (int dj = 0; dj < 4; dj++) {
                        const float rf = (float)(r0 + jh * 64 + tx * 4 + dj);
                        float s = sa[q][jh * 4 + dj];
                        float w = 1.f;
                        if (rf == bl)       w += wl;
                        if (rf == br)       w += wr;
                        if (rf == al + 1.f) w += dist;
                        if (rf == al)       w += 1.f - dist;
                        s *= w;
                        if (rf < bl || rf > br) s = -1e8f;
                        sa[q][jh * 4 + dj] = s;
                        rowm = fmaxf(rowm, s);
                    }
#pragma unroll
                for (int o = 8; o; o >>= 1)
                    rowm = fmaxf(rowm, __shfl_xor_sync(0xffffffffu, rowm, o));

                const float mnew = fmaxf(mrun[q], rowm);
                const float alpha = __expf(mrun[q] - mnew);
                mrun[q] = mnew;

                float rsum = 0.f;
#pragma unroll
                for (int j = 0; j < 8; j++) {
                    float p = __expf(sa[q][j] - mnew);
                    sa[q][j] = p;
                    rsum += p;
                }
#pragma unroll
                for (int o = 8; o; o >>= 1)
                    rsum += __shfl_xor_sync(0xffffffffu, rsum, o);
                lrun[q] = lrun[q] * alpha + rsum;

#pragma unroll
                for (int c = 0; c < 4; c++) oa[q][c] *= alpha;

                *(float4*)&Ps[il * PSLD + tx * 4]       = *(float4*)&sa[q][0];
                *(float4*)&Ps[il * PSLD + 64 + tx * 4]  = *(float4*)&sa[q][4];
            }
        __syncthreads();

        const float* prow[8];
#pragma unroll
        for (int ih = 0; ih < 2; ih++)
#pragma unroll
            for (int di = 0; di < 4; di++)
                prow[ih * 4 + di] = Ps + (ih * 64 + ty * 4 + di) * PSLD;

#pragma unroll 4
        for (int r = 0; r < 128; r += 2) {
            float4 bv0 = *(float4*)&Vs[r * 64 + tx * 4];
            float4 bv1 = *(float4*)&Vs[(r + 1) * 64 + tx * 4];
#pragma unroll
            for (int q = 0; q < 8; q++) {
                float2 av = *(const float2*)(prow[q] + r);
                oa[q][0] = fmaf(av.x, bv0.x, oa[q][0]);
                oa[q][1] = fmaf(av.x, bv0.y, oa[q][1]);
                oa[q][2] = fmaf(av.x, bv0.z, oa[q][2]);
                oa[q][3] = fmaf(av.x, bv0.w, oa[q][3]);
                oa[q][0] = fmaf(av.y, bv1.x, oa[q][0]);
                oa[q][1] = fmaf(av.y, bv1.y, oa[q][1]);
                oa[q][2] = fmaf(av.y, bv1.z, oa[q][2]);
                oa[q][3] = fmaf(av.y, bv1.w, oa[q][3]);
            }
        }
    }

    float* O = g_attnout + (size_t)(b * T_) * E_ + h * HD_;
#pragma unroll
    for (int ih = 0; ih < 2; ih++)
#pragma unroll
        for (int di = 0; di < 4; di++) {
            const int q = ih * 4 + di;
            const int i = i0 + ih * 64 + ty * 4 + di;
            const float inv = 1.f / lrun[q];
            float4 v;
            v.x = oa[q][0] * inv; v.y = oa[q][1] * inv;
            v.z = oa[q][2] * inv; v.w = oa[q][3] * inv;
            *(float4*)&O[(size_t)i * E_ + tx * 4] = v;
        }
}

// ---------------- host launch ----------------------------------------------
extern "C" void kernel_launch(void* const* d_in, const int* in_sizes, int n_in,
                              void* d_out, int out_size)
{
    const float* x      = (const float*)d_in[0];
    const float* W_qkv  = (const float*)d_in[1];
    const float* b_qkv  = (const float*)d_in[2];
    const float* W_od   = (const float*)d_in[3];
    const float* b_od   = (const float*)d_in[4];
    const float* W_out  = (const float*)d_in[5];
    const float* b_out  = (const float*)d_in[6];
    const void*  lenp   = (const void*)d_in[7];
    float* out = (float*)d_out;

    static float* qkv_p = nullptr;
    static float* attnout_p = nullptr;
    static bool configured = false;
    const int FLASH_SMEM = (64 * 128 * 2 + 128 * 64 + 128 * PSLD + 128 * 6) * 4;
    if (!configured) {
        cudaGetSymbolAddress((void**)&qkv_p, g_qkv);
        cudaGetSymbolAddress((void**)&attnout_p, g_attnout);
        cudaFuncSetAttribute(flash_kernel,
                             cudaFuncAttributeMaxDynamicSharedMemorySize,
                             FLASH_SMEM);
        cudaFuncSetAttribute(gemm_mma,
                             cudaFuncAttributeMaxDynamicSharedMemorySize,
                             GSMEM);
        configured = true;
    }

    // 0) fused od projection weights (fp32-exact path for band params)
    wc_kernel<<<16, 512>>>(W_qkv, b_qkv, W_od, b_od);

    // 1) qkv = x @ W_qkv + b_qkv    (2048 x 1536 x 512) — mma.sync bf16-split
    gemm_mma<<<dim3(QKVLD / 64, (B_ * T_) / 128), 256, GSMEM>>>(
        E_, x, E_, W_qkv, QKVLD, b_qkv, qkv_p, QKVLD);

    // 2) per-(head,query) band parameters from x @ Wc + bc (fp32)
    params_kernel<<<B_ * T_, 512>>>(x, lenp);

    // 3) fused attention: scores + point-weight + mask + softmax + @V
    flash_kernel<<<dim3(T_ / 128, BNH_), 256, FLASH_SMEM>>>();

    // 4) result = attn_out @ W_out + b_out  (2048 x 512 x 512) — mma.sync
    gemm_mma<<<dim3(E_ / 64, (B_ * T_) / 128), 256, GSMEM>>>(
        E_, attnout_p, E_, W_out, E_, b_out, out, E_);
}

// round 16
// speedup vs baseline: 2.1674x; 1.3568x over previous
#include <cuda_runtime.h>
#include <cuda_bf16.h>
#include <math.h>
#include <stdint.h>

#define B_   2
#define T_   1024
#define E_   512
#define NH_  8
#define HD_  64
#define BNH_ 16
#define QKVLD (3*E_)   // 1536

// ---------------- scratch (device globals: allocation-free) ----------------
__device__ float g_qkv[B_*T_*3*E_];          // (2048, 1536) rows = b*T+t
__device__ float g_params[BNH_*T_*6];        // per (g,t): bl, br, al, dist, bl-start, end-br
__device__ float g_attnout[B_*T_*E_];        // (2048, 512)
__device__ float g_wc[E_*2*NH_];             // fused od weights: (512, 16)
__device__ float g_bc[2*NH_];                // fused od bias

// ================= portable PTX helpers (base sm_103 target) ===============
__device__ __forceinline__ uint32_t smem_u32(const void* p) {
    uint32_t a;
    asm("{ .reg .u64 t; cvta.to.shared.u64 t, %1; cvt.u32.u64 %0, t; }"
        : "=r"(a) : "l"(p));
    return a;
}
#define SW128(off) ((off) ^ (((off) >> 3) & 0x70))

__device__ __forceinline__ void ldsm4(uint32_t* r, uint32_t a) {
    asm volatile("ldmatrix.sync.aligned.m8n8.x4.shared.b16 {%0,%1,%2,%3}, [%4];"
                 : "=r"(r[0]), "=r"(r[1]), "=r"(r[2]), "=r"(r[3]) : "r"(a));
}
__device__ __forceinline__ void ldsm4t(uint32_t* r, uint32_t a) {
    asm volatile("ldmatrix.sync.aligned.m8n8.x4.trans.shared.b16 {%0,%1,%2,%3}, [%4];"
                 : "=r"(r[0]), "=r"(r[1]), "=r"(r[2]), "=r"(r[3]) : "r"(a));
}
__device__ __forceinline__ void mma_bf16(float* d, const uint32_t* a,
                                         uint32_t b0, uint32_t b1) {
    asm volatile(
        "mma.sync.aligned.m16n8k16.row.col.f32.bf16.bf16.f32 "
        "{%0,%1,%2,%3}, {%4,%5,%6,%7}, {%8,%9}, {%0,%1,%2,%3};"
        : "+f"(d[0]), "+f"(d[1]), "+f"(d[2]), "+f"(d[3])
        : "r"(a[0]), "r"(a[1]), "r"(a[2]), "r"(a[3]), "r"(b0), "r"(b1));
}
__device__ __forceinline__ uint32_t packbf(float x, float y) {
    __nv_bfloat162 t = __floats2bfloat162_rn(x, y);
    return *(uint32_t*)&t;
}
__device__ __forceinline__ void split2(float x, float y, uint32_t& hh, uint32_t& ll) {
    __nv_bfloat162 hb = __floats2bfloat162_rn(x, y);
    float2 hf = __bfloat1622float2(hb);
    __nv_bfloat162 lb = __floats2bfloat162_rn(x - hf.x, y - hf.y);
    hh = *(uint32_t*)&hb;
    ll = *(uint32_t*)&lb;
}

// ============ mma.sync GEMM + bias: C[M,N] = A[M,K] @ B[K,N] + bias ========
// fp32 via bf16 3-term split. CTA tile 128x64, 8 warps (4x2), warp tile 32x32.
#define GA_H 0
#define GA_L 16384
#define GB_H 32768
#define GB_L 40960
#define GSMEM 49152

__global__ __launch_bounds__(256) void gemm_mma(
    int K,
    const float* __restrict__ A, int lda,
    const float* __restrict__ Bm, int ldb,
    const float* __restrict__ bias,
    float* __restrict__ C, int ldc)
{
    extern __shared__ char smg[];
    const uint32_t sb = smem_u32(smg);
    const int tid = threadIdx.x, wid = tid >> 5, lane = tid & 31;
    const int m0 = blockIdx.y * 128, n0 = blockIdx.x * 64;
    const int wm = (wid & 3) * 32, wn = (wid >> 2) * 32;
    const int lrow = lane & 15, lu = lane >> 4;

    float acc[2][4][4];
#pragma unroll
    for (int mi = 0; mi < 2; mi++)
#pragma unroll
        for (int nj = 0; nj < 4; nj++)
#pragma unroll
            for (int e = 0; e < 4; e++) acc[mi][nj][e] = 0.f;

    for (int k0 = 0; k0 < K; k0 += 64) {
#pragma unroll
        for (int i = 0; i < 8; i++) {
            const int gid = i * 256 + tid;
            const int m = gid >> 4, k4 = gid & 15;
            float4 av = *(const float4*)&A[(size_t)(m0 + m) * lda + k0 + k4 * 4];
            uint32_t h0, l0, h1, l1;
            split2(av.x, av.y, h0, l0);
            split2(av.z, av.w, h1, l1);
            const uint32_t so = SW128((uint32_t)(m * 128 + k4 * 8));
            *(uint2*)(smg + GA_H + so) = make_uint2(h0, h1);
            *(uint2*)(smg + GA_L + so) = make_uint2(l0, l1);
        }
#pragma unroll
        for (int i = 0; i < 4; i++) {
            const int gid = i * 256 + tid;
            const int n = gid & 63, k4 = gid >> 6;
            const float* bp = &Bm[(size_t)(k0 + k4 * 4) * ldb + n0 + n];
            float f0 = bp[0];
            float f1 = bp[ldb];
            float f2 = bp[2 * (size_t)ldb];
            float f3 = bp[3 * (size_t)ldb];
            uint32_t h0, l0, h1, l1;
            split2(f0, f1, h0, l0);
            split2(f2, f3, h1, l1);
            const uint32_t so = SW128((uint32_t)(n * 128 + k4 * 8));
            *(uint2*)(smg + GB_H + so) = make_uint2(h0, h1);
            *(uint2*)(smg + GB_L + so) = make_uint2(l0, l1);
        }
        __syncthreads();

#pragma unroll
        for (int ks = 0; ks < 4; ks++) {
            const uint32_t uoff = (2 * ks + lu) * 16;
            uint32_t ah[2][4], al[2][4];
#pragma unroll
            for (int mi = 0; mi < 2; mi++) {
                const uint32_t off = SW128((uint32_t)((wm + mi * 16 + lrow) * 128) + uoff);
                ldsm4(ah[mi], sb + GA_H + off);
                ldsm4(al[mi], sb + GA_L + off);
            }
            uint32_t bh[2][4], bl[2][4];
#pragma unroll
            for (int nj2 = 0; nj2 < 2; nj2++) {
                const uint32_t off = SW128((uint32_t)((wn + nj2 * 16 + lrow) * 128) + uoff);
                ldsm4(bh[nj2], sb + GB_H + off);
                ldsm4(bl[nj2], sb + GB_L + off);
            }
#pragma unroll
            for (int mi = 0; mi < 2; mi++)
#pragma unroll
                for (int nj2 = 0; nj2 < 2; nj2++)
#pragma unroll
                    for (int hf = 0; hf < 2; hf++) {
                        float* d = acc[mi][nj2 * 2 + hf];
                        mma_bf16(d, ah[mi], bh[nj2][hf], bh[nj2][hf + 2]);
                        mma_bf16(d, ah[mi], bl[nj2][hf], bl[nj2][hf + 2]);
                        mma_bf16(d, al[mi], bh[nj2][hf], bh[nj2][hf + 2]);
                    }
        }
        __syncthreads();
    }

    const int g2 = lane >> 2, t2 = (lane & 3) * 2;
#pragma unroll
    for (int mi = 0; mi < 2; mi++)
#pragma unroll
        for (int nj = 0; nj < 4; nj++) {
            const int m = m0 + wm + mi * 16 + g2;
            const int n = n0 + wn + nj * 8 + t2;
            const float b0 = __ldg(&bias[n]), b1 = __ldg(&bias[n + 1]);
            float2 v0 = make_float2(acc[mi][nj][0] + b0, acc[mi][nj][1] + b1);
            float2 v1 = make_float2(acc[mi][nj][2] + b0, acc[mi][nj][3] + b1);
            *(float2*)&C[(size_t)m * ldc + n] = v0;
            *(float2*)&C[(size_t)(m + 8) * ldc + n] = v1;
        }
}

// ------------ fused od weights: Wc = W_qkv[:, :E] @ W_od ; bc = b_q@W_od+b_od
__global__ __launch_bounds__(512) void wc_kernel(
    const float* __restrict__ W_qkv, const float* __restrict__ b_qkv,
    const float* __restrict__ W_od, const float* __restrict__ b_od)
{
    const int tid = threadIdx.x;
    const int k = blockIdx.x * 32 + (tid >> 4);   // 0..511
    const int w = tid & 15;                        // 0..15
    float s = 0.f;
    for (int j = 0; j < E_; j++)
        s = fmaf(W_qkv[(size_t)k * QKVLD + j], W_od[j * (2 * NH_) + w], s);
    g_wc[k * (2 * NH_) + w] = s;
    if (blockIdx.x == 0 && tid < 2 * NH_) {
        float t = 0.f;
        for (int j = 0; j < E_; j++)
            t = fmaf(b_qkv[j], W_od[j * (2 * NH_) + tid], t);
        g_bc[tid] = t + b_od[tid];
    }
}

// ---------------- params: od = x @ Wc + bc (exact fp32 path) ---------------
__device__ __forceinline__ float decode_len(const void* p)
{
    int iv = *(const int*)p;
    if (iv > 0 && iv < (1 << 24)) return (float)iv;   // int32 scalar
    return __int_as_float(iv);                         // float32 scalar
}

__global__ void params_kernel(const float* __restrict__ x,
                              const void*  __restrict__ lenraw)
{
    const int row = blockIdx.x;              // 0..2047
    const int b = row >> 10, t = row & 1023;
    const int tid = threadIdx.x;
    const int w = tid >> 5, lane = tid & 31; // 16 warps, one per od column
    const float* q = x + (size_t)row * E_;

    float s = 0.f;
    for (int k = lane; k < E_; k += 32)
        s = fmaf(q[k], g_wc[k * (2 * NH_) + w], s);
#pragma unroll
    for (int o = 16; o; o >>= 1) s += __shfl_xor_sync(0xffffffffu, s, o);

    __shared__ float od[2 * NH_];
    if (lane == 0) od[w] = s + g_bc[w];
    __syncthreads();

    if (tid < NH_) {
        const int h = tid;
        const float len = decode_len(lenraw);
        float off = tanhf(od[h]) * len;
        float dur = (1.f / (1.f + expf(-od[NH_ + h]))) * len;
        float anchor = (float)t + off;
        float start = anchor - dur;
        float end   = anchor + dur;
        float bl = floorf(start);
        float br = ceilf(end);
        float al = floorf(anchor);
        float dist = anchor - al;
        int g = b * NH_ + h;
        float* p = g_params + (size_t)(g * T_ + t) * 6;
        p[0] = bl; p[1] = br; p[2] = al; p[3] = dist;
        p[4] = bl - start; p[5] = end - br;
    }
}

// ================= fused flash attention on mma.sync =======================
// One CTA per (128-query i-tile, head). 8 warps x 16 query rows.
// S = QK^T bf16 3-term split; P kept in S fragments (C-frag == A-frag
// identity); PV = Ph*Vh + Ph*Vl + Pl*Vh with V via ldmatrix.trans.
// Padded rows (72 bf16 = 144 B = 9 x 16B units) -> conflict-free ldmatrix.
#define FROW 72
#define FQH  0
#define FQL  (FQH + 128*FROW*2)
#define FKH  (FQL + 128*FROW*2)
#define FKL  (FKH + 128*FROW*2)
#define FVH  (FKL + 128*FROW*2)
#define FVL  (FVH + 128*FROW*2)
#define FPP  (FVL + 128*FROW*2)
#define FSMEM (FPP + 128*6*4)

__global__ __launch_bounds__(256, 1) void flash_mma()
{
    extern __shared__ char smf[];
    const uint32_t sb = smem_u32(smf);
    float* pp = (float*)(smf + FPP);

    const int g = blockIdx.y, b = g >> 3, h = g & 7;
    const int i0 = blockIdx.x * 128;
    const int tid = threadIdx.x, wid = tid >> 5, lane = tid & 31;
    const int lrow = lane & 15, lu = lane >> 4;
    const int g2 = lane >> 2, t2 = lane & 3;
    const int wm = wid * 16;

    const float* Qg = g_qkv + (size_t)(b * T_) * QKVLD + h * HD_;
    const float* Kg = g_qkv + (size_t)(b * T_) * QKVLD + E_ + h * HD_;
    const float* Vg = g_qkv + (size_t)(b * T_) * QKVLD + 2 * E_ + h * HD_;

    const int rrow = tid >> 1, rkh = (tid & 1) * 32;

    // ---- stage Q (scaled 1/8), split hi/lo ----
#pragma unroll
    for (int j = 0; j < 8; j++) {
        float4 v = *(const float4*)&Qg[(size_t)(i0 + rrow) * QKVLD + rkh + j * 4];
        v.x *= 0.125f; v.y *= 0.125f; v.z *= 0.125f; v.w *= 0.125f;
        uint32_t h0, l0, h1, l1;
        split2(v.x, v.y, h0, l0);
        split2(v.z, v.w, h1, l1);
        const uint32_t so = (uint32_t)(rrow * 144 + (rkh + j * 4) * 2);
        *(uint2*)(smf + FQH + so) = make_uint2(h0, h1);
        *(uint2*)(smf + FQL + so) = make_uint2(l0, l1);
    }
    for (int idx = tid; idx < 128 * 6; idx += 256)
        pp[idx] = g_params[(size_t)(g * T_ + i0) * 6 + idx];
    __syncthreads();

    // per-thread params for its two rows (wm+g2, wm+g2+8)
    float prm[2][6];
#pragma unroll
    for (int rh = 0; rh < 2; rh++)
#pragma unroll
        for (int e = 0; e < 6; e++)
            prm[rh][e] = pp[(wm + g2 + rh * 8) * 6 + e];

    float o[8][4];
    float mrun[2] = {-INFINITY, -INFINITY};
    float lrun[2] = {0.f, 0.f};
#pragma unroll
    for (int tn = 0; tn < 8; tn++)
#pragma unroll
        for (int e = 0; e < 4; e++) o[tn][e] = 0.f;

    for (int it = 0; it < T_ / 128; it++) {
        const int r0 = it * 128;

        // ---- stage K, V tile (regs -> smem, split hi/lo) ----
        float4 kv[8], vv[8];
#pragma unroll
        for (int j = 0; j < 8; j++) {
            kv[j] = *(const float4*)&Kg[(size_t)(r0 + rrow) * QKVLD + rkh + j * 4];
            vv[j] = *(const float4*)&Vg[(size_t)(r0 + rrow) * QKVLD + rkh + j * 4];
        }
        __syncthreads();   // previous tile's consumers done
#pragma unroll
        for (int j = 0; j < 8; j++) {
            const uint32_t so = (uint32_t)(rrow * 144 + (rkh + j * 4) * 2);
            uint32_t h0, l0, h1, l1;
            split2(kv[j].x, kv[j].y, h0, l0);
            split2(kv[j].z, kv[j].w, h1, l1);
            *(uint2*)(smf + FKH + so) = make_uint2(h0, h1);
            *(uint2*)(smf + FKL + so) = make_uint2(l0, l1);
            split2(vv[j].x, vv[j].y, h0, l0);
            split2(vv[j].z, vv[j].w, h1, l1);
            *(uint2*)(smf + FVH + so) = make_uint2(h0, h1);
            *(uint2*)(smf + FVL + so) = make_uint2(l0, l1);
        }
        __syncthreads();

        // ---- S = Q K^T (3-term bf16 split), warp rows wm..wm+15, cols 0..127
        float sa[16][4];
#pragma unroll
        for (int nj = 0; nj < 16; nj++)
#pragma unroll
            for (int e = 0; e < 4; e++) sa[nj][e] = 0.f;

#pragma unroll
        for (int ks = 0; ks < 4; ks++) {
            const uint32_t uoff = (uint32_t)(ks * 32 + lu * 16);
            uint32_t ah[4], al[4];
            ldsm4(ah, sb + FQH + (uint32_t)((wm + lrow) * 144) + uoff);
            ldsm4(al, sb + FQL + (uint32_t)((wm + lrow) * 144) + uoff);
#pragma unroll
            for (int nj2 = 0; nj2 < 8; nj2++) {
                uint32_t bh[4], bl[4];
                const uint32_t ko = (uint32_t)((nj2 * 16 + lrow) * 144) + uoff;
                ldsm4(bh, sb + FKH + ko);
                ldsm4(bl, sb + FKL + ko);
#pragma unroll
                for (int hf = 0; hf < 2; hf++) {
                    float* d = sa[nj2 * 2 + hf];
                    mma_bf16(d, ah, bh[hf], bh[hf + 2]);
                    mma_bf16(d, ah, bl[hf], bl[hf + 2]);
                    mma_bf16(d, al, bh[hf], bh[hf + 2]);
                }
            }
        }

        // ---- epilogue: weight, mask, online softmax (per row-half) ----
#pragma unroll
        for (int rh = 0; rh < 2; rh++) {
            const float pbl = prm[rh][0], pbr = prm[rh][1];
            const float pal = prm[rh][2], pds = prm[rh][3];
            const float pwl = prm[rh][4], pwr = prm[rh][5];

            float rowm = -INFINITY;
#pragma unroll
            for (int nj = 0; nj < 16; nj++)
#pragma unroll
                for (int e = 0; e < 2; e++) {
                    const float rf = (float)(r0 + 8 * nj + 2 * t2 + e);
                    float s = sa[nj][rh * 2 + e];
                    float w = 1.f;
                    if (rf == pbl)       w += pwl;
                    if (rf == pbr)       w += pwr;
                    if (rf == pal + 1.f) w += pds;
                    if (rf == pal)       w += 1.f - pds;
                    s *= w;
                    if (rf < pbl || rf > pbr) s = -1e8f;
                    sa[nj][rh * 2 + e] = s;
                    rowm = fmaxf(rowm, s);
                }
            rowm = fmaxf(rowm, __shfl_xor_sync(0xffffffffu, rowm, 1));
            rowm = fmaxf(rowm, __shfl_xor_sync(0xffffffffu, rowm, 2));

            const float mnew = fmaxf(mrun[rh], rowm);
            const float alpha = __expf(mrun[rh] - mnew);
            mrun[rh] = mnew;

            float rsum = 0.f;
#pragma unroll
            for (int nj = 0; nj < 16; nj++)
#pragma unroll
                for (int e = 0; e < 2; e++) {
                    const float p = __expf(sa[nj][rh * 2 + e] - mnew);
                    sa[nj][rh * 2 + e] = p;
                    rsum += p;
                }
            rsum += __shfl_xor_sync(0xffffffffu, rsum, 1);
            rsum += __shfl_xor_sync(0xffffffffu, rsum, 2);
            lrun[rh] = lrun[rh] * alpha + rsum;

#pragma unroll
            for (int tn = 0; tn < 8; tn++) {
                o[tn][rh * 2 + 0] *= alpha;
                o[tn][rh * 2 + 1] *= alpha;
            }
        }

        // ---- O += P V : A-frags straight from S fragments ----
#pragma unroll
        for (int kc = 0; kc < 8; kc++) {
            uint32_t pah[4], pal4[4];
            split2(sa[2 * kc][0],     sa[2 * kc][1],     pah[0], pal4[0]);
            split2(sa[2 * kc][2],     sa[2 * kc][3],     pah[1], pal4[1]);
            split2(sa[2 * kc + 1][0], sa[2 * kc + 1][1], pah[2], pal4[2]);
            split2(sa[2 * kc + 1][2], sa[2 * kc + 1][3], pah[3], pal4[3]);
#pragma unroll
            for (int njv = 0; njv < 4; njv++) {
                uint32_t vh4[4], vl4[4];
                const uint32_t vo = (uint32_t)((kc * 16 + lrow) * 144 + njv * 32 + lu * 16);
                ldsm4t(vh4, sb + FVH + vo);
                ldsm4t(vl4, sb + FVL + vo);
#pragma unroll
                for (int q2 = 0; q2 < 2; q2++) {
                    float* d = o[njv * 2 + q2];
                    mma_bf16(d, pah, vh4[q2 * 2], vh4[q2 * 2 + 1]);
                    mma_bf16(d, pah, vl4[q2 * 2], vl4[q2 * 2 + 1]);
                    mma_bf16(d, pal4, vh4[q2 * 2], vh4[q2 * 2 + 1]);
                }
            }
        }
    }

    // ---- normalize and write out (b, t, e) ----
#pragma unroll
    for (int rh = 0; rh < 2; rh++) {
        const int row = i0 + wm + g2 + rh * 8;
        const float inv = 1.f / lrun[rh];
        float* O = g_attnout + (size_t)(b * T_ + row) * E_ + h * HD_;
#pragma unroll
        for (int tn = 0; tn < 8; tn++) {
            float2 v;
            v.x = o[tn][rh * 2 + 0] * inv;
            v.y = o[tn][rh * 2 + 1] * inv;
            *(float2*)&O[tn * 8 + t2 * 2] = v;
        }
    }
}

// ---------------- host launch ----------------------------------------------
extern "C" void kernel_launch(void* const* d_in, const int* in_sizes, int n_in,
                              void* d_out, int out_size)
{
    const float* x      = (const float*)d_in[0];
    const float* W_qkv  = (const float*)d_in[1];
    const float* b_qkv  = (const float*)d_in[2];
    const float* W_od   = (const float*)d_in[3];
    const float* b_od   = (const float*)d_in[4];
    const float* W_out  = (const float*)d_in[5];
    const float* b_out  = (const float*)d_in[6];
    const void*  lenp   = (const void*)d_in[7];
    float* out = (float*)d_out;

    static float* qkv_p = nullptr;
    static float* attnout_p = nullptr;
    static bool configured = false;
    if (!configured) {
        cudaGetSymbolAddress((void**)&qkv_p, g_qkv);
        cudaGetSymbolAddress((void**)&attnout_p, g_attnout);
        cudaFuncSetAttribute(flash_mma,
                             cudaFuncAttributeMaxDynamicSharedMemorySize,
                             FSMEM);
        cudaFuncSetAttribute(gemm_mma,
                             cudaFuncAttributeMaxDynamicSharedMemorySize,
                             GSMEM);
        configured = true;
    }

    // 0) fused od projection weights (fp32-exact path for band params)
    wc_kernel<<<16, 512>>>(W_qkv, b_qkv, W_od, b_od);

    // 1) qkv = x @ W_qkv + b_qkv    (2048 x 1536 x 512) — mma.sync bf16-split
    gemm_mma<<<dim3(QKVLD / 64, (B_ * T_) / 128), 256, GSMEM>>>(
        E_, x, E_, W_qkv, QKVLD, b_qkv, qkv_p, QKVLD);

    // 2) per-(head,query) band parameters from x @ Wc + bc (fp32)
    params_kernel<<<B_ * T_, 512>>>(x, lenp);

    // 3) fused attention on tensor cores
    flash_mma<<<dim3(T_ / 128, BNH_), 256, FSMEM>>>();

    // 4) result = attn_out @ W_out + b_out  (2048 x 512 x 512) — mma.sync
    gemm_mma<<<dim3(E_ / 64, (B_ * T_) / 128), 256, GSMEM>>>(
        E_, attnout_p, E_, W_out, E_, b_out, out, E_);
}

// round 17
// speedup vs baseline: 2.3722x; 1.0945x over previous
#include <cuda_runtime.h>
#include <cuda_bf16.h>
#include <math.h>
#include <stdint.h>

#define B_   2
#define T_   1024
#define E_   512
#define NH_  8
#define HD_  64
#define BNH_ 16
#define QKVLD (3*E_)   // 1536

// ---------------- scratch (device globals: allocation-free) ----------------
// Q/K/V stored ONLY as bf16 hi/lo pairs in flash-native [head][t][64] layout.
__device__ uint32_t g_qh[BNH_*T_*HD_/2];
__device__ uint32_t g_ql[BNH_*T_*HD_/2];
__device__ uint32_t g_kh[BNH_*T_*HD_/2];
__device__ uint32_t g_kl[BNH_*T_*HD_/2];
__device__ uint32_t g_vh[BNH_*T_*HD_/2];
__device__ uint32_t g_vl[BNH_*T_*HD_/2];
__device__ float g_params[BNH_*T_*6];        // per (g,t): bl, br, al, dist, bl-start, end-br
__device__ float g_attnout[B_*T_*E_];        // (2048, 512)
__device__ float g_wc[E_*2*NH_];             // fused od weights: (512, 16)
__device__ float g_bc[2*NH_];                // fused od bias

// ================= portable PTX helpers (base sm_103 target) ===============
__device__ __forceinline__ uint32_t smem_u32(const void* p) {
    uint32_t a;
    asm("{ .reg .u64 t; cvta.to.shared.u64 t, %1; cvt.u32.u64 %0, t; }"
        : "=r"(a) : "l"(p));
    return a;
}
#define SW128(off) ((off) ^ (((off) >> 3) & 0x70))

__device__ __forceinline__ void ldsm4(uint32_t* r, uint32_t a) {
    asm volatile("ldmatrix.sync.aligned.m8n8.x4.shared.b16 {%0,%1,%2,%3}, [%4];"
                 : "=r"(r[0]), "=r"(r[1]), "=r"(r[2]), "=r"(r[3]) : "r"(a));
}
__device__ __forceinline__ void ldsm4t(uint32_t* r, uint32_t a) {
    asm volatile("ldmatrix.sync.aligned.m8n8.x4.trans.shared.b16 {%0,%1,%2,%3}, [%4];"
                 : "=r"(r[0]), "=r"(r[1]), "=r"(r[2]), "=r"(r[3]) : "r"(a));
}
__device__ __forceinline__ void mma_bf16(float* d, const uint32_t* a,
                                         uint32_t b0, uint32_t b1) {
    asm volatile(
        "mma.sync.aligned.m16n8k16.row.col.f32.bf16.bf16.f32 "
        "{%0,%1,%2,%3}, {%4,%5,%6,%7}, {%8,%9}, {%0,%1,%2,%3};"
        : "+f"(d[0]), "+f"(d[1]), "+f"(d[2]), "+f"(d[3])
        : "r"(a[0]), "r"(a[1]), "r"(a[2]), "r"(a[3]), "r"(b0), "r"(b1));
}
__device__ __forceinline__ void split2(float x, float y, uint32_t& hh, uint32_t& ll) {
    __nv_bfloat162 hb = __floats2bfloat162_rn(x, y);
    float2 hf = __bfloat1622float2(hb);
    __nv_bfloat162 lb = __floats2bfloat162_rn(x - hf.x, y - hf.y);
    hh = *(uint32_t*)&hb;
    ll = *(uint32_t*)&lb;
}
__device__ __forceinline__ void cpasync16(uint32_t saddr, const void* gaddr) {
    asm volatile("cp.async.cg.shared.global [%0], [%1], 16;"
                 :: "r"(saddr), "l"(gaddr) : "memory");
}
#define CP_COMMIT() asm volatile("cp.async.commit_group;" ::: "memory")
#define CP_WAIT(n)  asm volatile("cp.async.wait_group %0;" :: "n"(n) : "memory")

// ============ mma.sync GEMM + bias =========================================
// fp32 via bf16 3-term split. CTA tile 128x64, 8 warps (4x2), warp tile 32x32.
// QKV=true: epilogue writes Q(scaled)/K/V as bf16 hi/lo to g_q*/g_k*/g_v*.
// QKV=false: epilogue writes fp32 C.
#define GA_H 0
#define GA_L 16384
#define GB_H 32768
#define GB_L 40960
#define GSMEM 49152

template <bool QKV>
__global__ __launch_bounds__(256) void gemm_mma(
    int K,
    const float* __restrict__ A, int lda,
    const float* __restrict__ Bm, int ldb,
    const float* __restrict__ bias,
    float* __restrict__ C, int ldc)
{
    extern __shared__ char smg[];
    const uint32_t sb = smem_u32(smg);
    const int tid = threadIdx.x, wid = tid >> 5, lane = tid & 31;
    const int m0 = blockIdx.y * 128, n0 = blockIdx.x * 64;
    const int wm = (wid & 3) * 32, wn = (wid >> 2) * 32;
    const int lrow = lane & 15, lu = lane >> 4;

    float acc[2][4][4];
#pragma unroll
    for (int mi = 0; mi < 2; mi++)
#pragma unroll
        for (int nj = 0; nj < 4; nj++)
#pragma unroll
            for (int e = 0; e < 4; e++) acc[mi][nj][e] = 0.f;

    for (int k0 = 0; k0 < K; k0 += 64) {
#pragma unroll
        for (int i = 0; i < 8; i++) {
            const int gid = i * 256 + tid;
            const int m = gid >> 4, k4 = gid & 15;
            float4 av = *(const float4*)&A[(size_t)(m0 + m) * lda + k0 + k4 * 4];
            uint32_t h0, l0, h1, l1;
            split2(av.x, av.y, h0, l0);
            split2(av.z, av.w, h1, l1);
            const uint32_t so = SW128((uint32_t)(m * 128 + k4 * 8));
            *(uint2*)(smg + GA_H + so) = make_uint2(h0, h1);
            *(uint2*)(smg + GA_L + so) = make_uint2(l0, l1);
        }
#pragma unroll
        for (int i = 0; i < 4; i++) {
            const int gid = i * 256 + tid;
            const int n = gid & 63, k4 = gid >> 6;
            const float* bp = &Bm[(size_t)(k0 + k4 * 4) * ldb + n0 + n];
            float f0 = bp[0];
            float f1 = bp[ldb];
            float f2 = bp[2 * (size_t)ldb];
            float f3 = bp[3 * (size_t)ldb];
            uint32_t h0, l0, h1, l1;
            split2(f0, f1, h0, l0);
            split2(f2, f3, h1, l1);
            const uint32_t so = SW128((uint32_t)(n * 128 + k4 * 8));
            *(uint2*)(smg + GB_H + so) = make_uint2(h0, h1);
            *(uint2*)(smg + GB_L + so) = make_uint2(l0, l1);
        }
        __syncthreads();

#pragma unroll
        for (int ks = 0; ks < 4; ks++) {
            const uint32_t uoff = (2 * ks + lu) * 16;
            uint32_t ah[2][4], al[2][4];
#pragma unroll
            for (int mi = 0; mi < 2; mi++) {
                const uint32_t off = SW128((uint32_t)((wm + mi * 16 + lrow) * 128) + uoff);
                ldsm4(ah[mi], sb + GA_H + off);
                ldsm4(al[mi], sb + GA_L + off);
            }
            uint32_t bh[2][4], bl[2][4];
#pragma unroll
            for (int nj2 = 0; nj2 < 2; nj2++) {
                const uint32_t off = SW128((uint32_t)((wn + nj2 * 16 + lrow) * 128) + uoff);
                ldsm4(bh[nj2], sb + GB_H + off);
                ldsm4(bl[nj2], sb + GB_L + off);
            }
#pragma unroll
            for (int mi = 0; mi < 2; mi++)
#pragma unroll
                for (int nj2 = 0; nj2 < 2; nj2++)
#pragma unroll
                    for (int hf = 0; hf < 2; hf++) {
                        float* d = acc[mi][nj2 * 2 + hf];
                        mma_bf16(d, ah[mi], bh[nj2][hf], bh[nj2][hf + 2]);
                        mma_bf16(d, ah[mi], bl[nj2][hf], bl[nj2][hf + 2]);
                        mma_bf16(d, al[mi], bh[nj2][hf], bh[nj2][hf + 2]);
                    }
        }
        __syncthreads();
    }

    const int g2 = lane >> 2, t2 = (lane & 3) * 2;
#pragma unroll
    for (int mi = 0; mi < 2; mi++)
#pragma unroll
        for (int nj = 0; nj < 4; nj++) {
            const int m = m0 + wm + mi * 16 + g2;
            const int n = n0 + wn + nj * 8 + t2;
            const float b0 = __ldg(&bias[n]), b1 = __ldg(&bias[n + 1]);
            float x0 = acc[mi][nj][0] + b0, x1 = acc[mi][nj][1] + b1;
            float y0 = acc[mi][nj][2] + b0, y1 = acc[mi][nj][3] + b1;
            if (QKV) {
                const int sec = n >> 9, h = (n >> 6) & 7, c = n & 63;
                if (sec == 0) { x0 *= 0.125f; x1 *= 0.125f; y0 *= 0.125f; y1 *= 0.125f; }
                uint32_t* H; uint32_t* L;
                if (sec == 0)      { H = g_qh; L = g_ql; }
                else if (sec == 1) { H = g_kh; L = g_kl; }
                else               { H = g_vh; L = g_vl; }
                const int bb = m >> 10, tt = m & 1023;
                const size_t off = ((size_t)(bb * NH_ + h) * T_ + tt) * 32 + (c >> 1);
                uint32_t hh, ll;
                split2(x0, x1, hh, ll);
                H[off] = hh; L[off] = ll;
                split2(y0, y1, hh, ll);
                H[off + 8 * 32] = hh; L[off + 8 * 32] = ll;
            } else {
                *(float2*)&C[(size_t)m * ldc + n] = make_float2(x0, x1);
                *(float2*)&C[(size_t)(m + 8) * ldc + n] = make_float2(y0, y1);
            }
        }
}

// ------------ fused od weights: Wc = W_qkv[:, :E] @ W_od ; bc = b_q@W_od+b_od
__global__ __launch_bounds__(512) void wc_kernel(
    const float* __restrict__ W_qkv, const float* __restrict__ b_qkv,
    const float* __restrict__ W_od, const float* __restrict__ b_od)
{
    const int tid = threadIdx.x;
    const int k = blockIdx.x * 32 + (tid >> 4);   // 0..511
    const int w = tid & 15;                        // 0..15
    float s = 0.f;
    for (int j = 0; j < E_; j++)
        s = fmaf(W_qkv[(size_t)k * QKVLD + j], W_od[j * (2 * NH_) + w], s);
    g_wc[k * (2 * NH_) + w] = s;
    if (blockIdx.x == 0 && tid < 2 * NH_) {
        float t = 0.f;
        for (int j = 0; j < E_; j++)
            t = fmaf(b_qkv[j], W_od[j * (2 * NH_) + tid], t);
        g_bc[tid] = t + b_od[tid];
    }
}

// ---------------- params: od = x @ Wc + bc (exact fp32 path) ---------------
__device__ __forceinline__ float decode_len(const void* p)
{
    int iv = *(const int*)p;
    if (iv > 0 && iv < (1 << 24)) return (float)iv;   // int32 scalar
    return __int_as_float(iv);                         // float32 scalar
}

__global__ void params_kernel(const float* __restrict__ x,
                              const void*  __restrict__ lenraw)
{
    const int row = blockIdx.x;              // 0..2047
    const int b = row >> 10, t = row & 1023;
    const int tid = threadIdx.x;
    const int w = tid >> 5, lane = tid & 31; // 16 warps, one per od column
    const float* q = x + (size_t)row * E_;

    float s = 0.f;
    for (int k = lane; k < E_; k += 32)
        s = fmaf(q[k], g_wc[k * (2 * NH_) + w], s);
#pragma unroll
    for (int o = 16; o; o >>= 1) s += __shfl_xor_sync(0xffffffffu, s, o);

    __shared__ float od[2 * NH_];
    if (lane == 0) od[w] = s + g_bc[w];
    __syncthreads();

    if (tid < NH_) {
        const int h = tid;
        const float len = decode_len(lenraw);
        float off = tanhf(od[h]) * len;
        float dur = (1.f / (1.f + expf(-od[NH_ + h]))) * len;
        float anchor = (float)t + off;
        float start = anchor - dur;
        float end   = anchor + dur;
        float bl = floorf(start);
        float br = ceilf(end);
        float al = floorf(anchor);
        float dist = anchor - al;
        int g = b * NH_ + h;
        float* p = g_params + (size_t)(g * T_ + t) * 6;
        p[0] = bl; p[1] = br; p[2] = al; p[3] = dist;
        p[4] = bl - start; p[5] = end - br;
    }
}

// ================= fused flash attention on mma.sync + cp.async ============
// Q/K/V arrive pre-split bf16 hi/lo. K/V double-buffered via cp.async.
// Padded rows (72 bf16 = 144 B = 9 x 16B units) -> conflict-free ldmatrix.
#define FTILE 18432            // one 128x144B tile
#define FQH 0
#define FQL FTILE
#define FPP (10*FTILE)
#define FSMEM (FPP + 128*6*4)

__device__ __forceinline__ void stage_kv(uint32_t sb, int tid,
    const char* kh, const char* kl, const char* vh, const char* vl,
    int r0, int buf)
{
    const uint32_t kvb = 2 * FTILE + (uint32_t)buf * 4 * FTILE;
#pragma unroll
    for (int j = 0; j < 16; j++) {
        const int arr = j >> 2;                 // compile-time after unroll
        const int rem = tid + (j & 3) * 256;
        const int row = rem >> 3, ch = rem & 7;
        const char* src;
        switch (arr) {
            case 0:  src = kh; break;
            case 1:  src = kl; break;
            case 2:  src = vh; break;
            default: src = vl; break;
        }
        src += (size_t)(r0 + row) * 128 + ch * 16;
        cpasync16(sb + kvb + (uint32_t)arr * FTILE + row * 144 + ch * 16, src);
    }
}

__global__ __launch_bounds__(256, 1) void flash_mma()
{
    extern __shared__ char smf[];
    const uint32_t sb = smem_u32(smf);
    float* pp = (float*)(smf + FPP);

    const int g = blockIdx.y, b = g >> 3, h = g & 7;
    const int i0 = blockIdx.x * 128;
    const int tid = threadIdx.x, wid = tid >> 5, lane = tid & 31;
    const int lrow = lane & 15, lu = lane >> 4;
    const int g2 = lane >> 2, t2 = lane & 3;
    const int wm = wid * 16;

    const char* qh_g = (const char*)g_qh + (size_t)(g * T_ + i0) * 128;
    const char* ql_g = (const char*)g_ql + (size_t)(g * T_ + i0) * 128;
    const char* kh_g = (const char*)g_kh + (size_t)(g * T_) * 128;
    const char* kl_g = (const char*)g_kl + (size_t)(g * T_) * 128;
    const char* vh_g = (const char*)g_vh + (size_t)(g * T_) * 128;
    const char* vl_g = (const char*)g_vl + (size_t)(g * T_) * 128;

    // ---- stage Q (hi/lo) + first K/V tile via cp.async ----
#pragma unroll
    for (int j = 0; j < 8; j++) {
        const int arr = j >> 2;
        const int rem = tid + (j & 3) * 256;
        const int row = rem >> 3, ch = rem & 7;
        const char* src = (arr ? ql_g : qh_g) + (size_t)row * 128 + ch * 16;
        cpasync16(sb + (arr ? FQL : FQH) + row * 144 + ch * 16, src);
    }
    stage_kv(sb, tid, kh_g, kl_g, vh_g, vl_g, 0, 0);
    CP_COMMIT();

    for (int idx = tid; idx < 128 * 6; idx += 256)
        pp[idx] = g_params[(size_t)(g * T_ + i0) * 6 + idx];
    __syncthreads();

    float prm[2][6];
#pragma unroll
    for (int rh = 0; rh < 2; rh++)
#pragma unroll
        for (int e = 0; e < 6; e++)
            prm[rh][e] = pp[(wm + g2 + rh * 8) * 6 + e];

    float o[8][4];
    float mrun[2] = {-INFINITY, -INFINITY};
    float lrun[2] = {0.f, 0.f};
#pragma unroll
    for (int tn = 0; tn < 8; tn++)
#pragma unroll
        for (int e = 0; e < 4; e++) o[tn][e] = 0.f;

    for (int it = 0; it < T_ / 128; it++) {
        const int r0 = it * 128;

        if (it + 1 < T_ / 128) {
            stage_kv(sb, tid, kh_g, kl_g, vh_g, vl_g, r0 + 128, (it + 1) & 1);
            CP_COMMIT();
            CP_WAIT(1);
        } else {
            CP_WAIT(0);
        }
        __syncthreads();

        const uint32_t kvb = 2 * FTILE + (uint32_t)(it & 1) * 4 * FTILE;
        const uint32_t sKH = sb + kvb;
        const uint32_t sKL = sKH + FTILE;
        const uint32_t sVH = sKL + FTILE;
        const uint32_t sVL = sVH + FTILE;

        // ---- S = Q K^T (3-term bf16 split) ----
        float sa[16][4];
#pragma unroll
        for (int nj = 0; nj < 16; nj++)
#pragma unroll
            for (int e = 0; e < 4; e++) sa[nj][e] = 0.f;

#pragma unroll
        for (int ks = 0; ks < 4; ks++) {
            const uint32_t uoff = (uint32_t)(ks * 32 + lu * 16);
            uint32_t ah[4], al[4];
            ldsm4(ah, sb + FQH + (uint32_t)((wm + lrow) * 144) + uoff);
            ldsm4(al, sb + FQL + (uint32_t)((wm + lrow) * 144) + uoff);
#pragma unroll
            for (int nj2 = 0; nj2 < 8; nj2++) {
                uint32_t bh[4], bl[4];
                const uint32_t ko = (uint32_t)((nj2 * 16 + lrow) * 144) + uoff;
                ldsm4(bh, sKH + ko);
                ldsm4(bl, sKL + ko);
#pragma unroll
                for (int hf = 0; hf < 2; hf++) {
                    float* d = sa[nj2 * 2 + hf];
                    mma_bf16(d, ah, bh[hf], bh[hf + 2]);
                    mma_bf16(d, ah, bl[hf], bl[hf + 2]);
                    mma_bf16(d, al, bh[hf], bh[hf + 2]);
                }
            }
        }

        // ---- epilogue: weight, mask, online softmax (per row-half) ----
#pragma unroll
        for (int rh = 0; rh < 2; rh++) {
            const float pbl = prm[rh][0], pbr = prm[rh][1];
            const float pal = prm[rh][2], pds = prm[rh][3];
            const float pwl = prm[rh][4], pwr = prm[rh][5];

            float rowm = -INFINITY;
#pragma unroll
            for (int nj = 0; nj < 16; nj++)
#pragma unroll
                for (int e = 0; e < 2; e++) {
                    const float rf = (float)(r0 + 8 * nj + 2 * t2 + e);
                    float s = sa[nj][rh * 2 + e];
                    float w = 1.f;
                    if (rf == pbl)       w += pwl;
                    if (rf == pbr)       w += pwr;
                    if (rf == pal + 1.f) w += pds;
                    if (rf == pal)       w += 1.f - pds;
                    s *= w;
                    if (rf < pbl || rf > pbr) s = -1e8f;
                    sa[nj][rh * 2 + e] = s;
                    rowm = fmaxf(rowm, s);
                }
            rowm = fmaxf(rowm, __shfl_xor_sync(0xffffffffu, rowm, 1));
            rowm = fmaxf(rowm, __shfl_xor_sync(0xffffffffu, rowm, 2));

            const float mnew = fmaxf(mrun[rh], rowm);
            const float alpha = __expf(mrun[rh] - mnew);
            mrun[rh] = mnew;

            float rsum = 0.f;
#pragma unroll
            for (int nj = 0; nj < 16; nj++)
#pragma unroll
                for (int e = 0; e < 2; e++) {
                    const float p = __expf(sa[nj][rh * 2 + e] - mnew);
                    sa[nj][rh * 2 + e] = p;
                    rsum += p;
                }
            rsum += __shfl_xor_sync(0xffffffffu, rsum, 1);
            rsum += __shfl_xor_sync(0xffffffffu, rsum, 2);
            lrun[rh] = lrun[rh] * alpha + rsum;

#pragma unroll
            for (int tn = 0; tn < 8; tn++) {
                o[tn][rh * 2 + 0] *= alpha;
                o[tn][rh * 2 + 1] *= alpha;
            }
        }

        // ---- O += P V : A-frags straight from S fragments ----
#pragma unroll
        for (int kc = 0; kc < 8; kc++) {
            uint32_t pah[4], pal4[4];
            split2(sa[2 * kc][0],     sa[2 * kc][1],     pah[0], pal4[0]);
            split2(sa[2 * kc][2],     sa[2 * kc][3],     pah[1], pal4[1]);
            split2(sa[2 * kc + 1][0], sa[2 * kc + 1][1], pah[2], pal4[2]);
            split2(sa[2 * kc + 1][2], sa[2 * kc + 1][3], pah[3], pal4[3]);
#pragma unroll
            for (int njv = 0; njv < 4; njv++) {
                uint32_t vh4[4], vl4[4];
                const uint32_t vo = (uint32_t)((kc * 16 + lrow) * 144 + njv * 32 + lu * 16);
                ldsm4t(vh4, sVH + vo);
                ldsm4t(vl4, sVL + vo);
#pragma unroll
                for (int q2 = 0; q2 < 2; q2++) {
                    float* d = o[njv * 2 + q2];
                    mma_bf16(d, pah, vh4[q2 * 2], vh4[q2 * 2 + 1]);
                    mma_bf16(d, pah, vl4[q2 * 2], vl4[q2 * 2 + 1]);
                    mma_bf16(d, pal4, vh4[q2 * 2], vh4[q2 * 2 + 1]);
                }
            }
        }
        __syncthreads();   // all reads of buf[it&1] done before restage at it+2
    }

    // ---- normalize and write out (b, t, e) ----
#pragma unroll
    for (int rh = 0; rh < 2; rh++) {
        const int row = i0 + wm + g2 + rh * 8;
        const float inv = 1.f / lrun[rh];
        float* O = g_attnout + (size_t)(b * T_ + row) * E_ + h * HD_;
#pragma unroll
        for (int tn = 0; tn < 8; tn++) {
            float2 v;
            v.x = o[tn][rh * 2 + 0] * inv;
            v.y = o[tn][rh * 2 + 1] * inv;
            *(float2*)&O[tn * 8 + t2 * 2] = v;
        }
    }
}

// ---------------- host launch ----------------------------------------------
extern "C" void kernel_launch(void* const* d_in, const int* in_sizes, int n_in,
                              void* d_out, int out_size)
{
    const float* x      = (const float*)d_in[0];
    const float* W_qkv  = (const float*)d_in[1];
    const float* b_qkv  = (const float*)d_in[2];
    const float* W_od   = (const float*)d_in[3];
    const float* b_od   = (const float*)d_in[4];
    const float* W_out  = (const float*)d_in[5];
    const float* b_out  = (const float*)d_in[6];
    const void*  lenp   = (const void*)d_in[7];
    float* out = (float*)d_out;

    static float* attnout_p = nullptr;
    static bool configured = false;
    if (!configured) {
        cudaGetSymbolAddress((void**)&attnout_p, g_attnout);
        cudaFuncSetAttribute(flash_mma,
                             cudaFuncAttributeMaxDynamicSharedMemorySize,
                             FSMEM);
        cudaFuncSetAttribute(gemm_mma<true>,
                             cudaFuncAttributeMaxDynamicSharedMemorySize,
                             GSMEM);
        cudaFuncSetAttribute(gemm_mma<false>,
                             cudaFuncAttributeMaxDynamicSharedMemorySize,
                             GSMEM);
        configured = true;
    }

    // 0) fused od projection weights (fp32-exact path for band params)
    wc_kernel<<<16, 512>>>(W_qkv, b_qkv, W_od, b_od);

    // 1) qkv GEMM -> writes Q(scaled)/K/V directly as bf16 hi/lo arrays
    gemm_mma<true><<<dim3(QKVLD / 64, (B_ * T_) / 128), 256, GSMEM>>>(
        E_, x, E_, W_qkv, QKVLD, b_qkv, nullptr, 0);

    // 2) per-(head,query) band parameters from x @ Wc + bc (fp32)
    params_kernel<<<B_ * T_, 512>>>(x, lenp);

    // 3) fused attention on tensor cores (cp.async double-buffered K/V)
    flash_mma<<<dim3(T_ / 128, BNH_), 256, FSMEM>>>();

    // 4) result = attn_out @ W_out + b_out  (2048 x 512 x 512) — mma.sync
    gemm_mma<false><<<dim3(E_ / 64, (B_ * T_) / 128), 256, GSMEM>>>(
        E_, attnout_p, E_, W_out, E_, b_out, out, E_);
}